// round 4
// baseline (speedup 1.0000x reference)
#include <cuda_runtime.h>
#include <math.h>
#include <stdint.h>

#define BB 4096
#define LAT 256
#define HH 512
#define AA 64
#define LL 128
#define NG 2048          // gate gemm N: [r | z | n_x | n_h]
#define KG 576           // gate gemm K: [x(64) | h(512)]

// ---- scratch (static device globals; total ~2.35 GB, under aarch64 reloc limit) ----
__device__ float    g_Hall[(size_t)LL * BB * HH];         // 1.07 GB
__device__ float    g_P1[(size_t)(LL - 1) * BB * HH];     // 1.06 GB
__device__ float    g_P2[(size_t)(LL - 1) * BB * AA];     // 133 MB
__device__ float    g_gates[(size_t)BB * NG];             // 33.5 MB (reused per step)
__device__ float    g_xbos[(size_t)BB * AA];
__device__ float    g_t1[(size_t)BB * HH];
__device__ float    g_t2[(size_t)BB * HH];
// pre-split tf32 weights (hi/lo)
__device__ uint32_t g_Wcat_hi[(size_t)NG * KG];           // 4.7 MB
__device__ uint32_t g_Wcat_lo[(size_t)NG * KG];
__device__ uint32_t g_Wd1_hi[HH * LAT], g_Wd1_lo[HH * LAT];
__device__ uint32_t g_Wd2_hi[HH * HH],  g_Wd2_lo[HH * HH];
__device__ uint32_t g_Wd3_hi[HH * HH],  g_Wd3_lo[HH * HH];
__device__ uint32_t g_Wm1_hi[HH * HH],  g_Wm1_lo[HH * HH];
__device__ uint32_t g_Wm2_hi[AA * HH],  g_Wm2_lo[AA * HH];
__device__ uint32_t g_Wm3_hi[AA * AA],  g_Wm3_lo[AA * AA];
__device__ float    g_biascat[NG];

// ============================================================
// tf32 helpers
// ============================================================
__device__ __forceinline__ uint32_t f2tf32(float f) {
    uint32_t r;
    asm("cvt.rna.tf32.f32 %0, %1;" : "=r"(r) : "f"(f));
    return r;
}
__device__ __forceinline__ void split_tf32(float v, uint32_t& hi, uint32_t& lo) {
    hi = f2tf32(v);
    float rem = v - __uint_as_float(hi);
    lo = f2tf32(rem);
}
__device__ __forceinline__ void mma8(float d[4], const uint32_t a[4],
                                     uint32_t b0, uint32_t b1) {
    asm volatile(
        "mma.sync.aligned.m16n8k8.row.col.f32.tf32.tf32.f32 "
        "{%0,%1,%2,%3},{%4,%5,%6,%7},{%8,%9},{%0,%1,%2,%3};"
        : "+f"(d[0]), "+f"(d[1]), "+f"(d[2]), "+f"(d[3])
        : "r"(a[0]), "r"(a[1]), "r"(a[2]), "r"(a[3]), "r"(b0), "r"(b1));
}

// ============================================================
// Setup kernels
// ============================================================
__global__ void fill_bos_out(float* __restrict__ out) {
    int idx = blockIdx.x * blockDim.x + threadIdx.x;   // [0, BB*AA)
    int b = idx >> 6;
    int a = idx & 63;
    out[(size_t)b * (LL * AA) + a] = (a == 0) ? 16.0f : -16.0f;
}
__global__ void fill_xbos(float* __restrict__ xb) {
    int idx = blockIdx.x * blockDim.x + threadIdx.x;
    xb[idx] = ((idx & 63) == 0) ? 16.0f : -16.0f;
}
// generic weight split
__global__ void split_w(const float* __restrict__ src, uint32_t* __restrict__ hi,
                        uint32_t* __restrict__ lo, int n) {
    int i = blockIdx.x * blockDim.x + threadIdx.x;
    if (i < n) {
        uint32_t h, l;
        split_tf32(src[i], h, l);
        hi[i] = h; lo[i] = l;
    }
}
// Wcat2[n][k]: n<1024 (r,z): [Wih[n]|Whh[n]]; 1024..1535 (n_x): [Wih[n]|0];
// 1536..2047 (n_h): [0|Whh[n-512]]
__global__ void build_wcat(const float* __restrict__ Wih, const float* __restrict__ Whh,
                           uint32_t* __restrict__ hi, uint32_t* __restrict__ lo) {
    int i = blockIdx.x * blockDim.x + threadIdx.x;     // [0, NG*KG)
    if (i >= NG * KG) return;
    int k = i % KG;
    int n = i / KG;
    float v = 0.0f;
    if (n < 1024)      v = (k < AA) ? Wih[n * AA + k] : Whh[(size_t)n * HH + k - AA];
    else if (n < 1536) v = (k < AA) ? Wih[n * AA + k] : 0.0f;
    else               v = (k < AA) ? 0.0f : Whh[(size_t)(n - 512) * HH + k - AA];
    uint32_t h, l;
    split_tf32(v, h, l);
    hi[i] = h; lo[i] = l;
}
// bias_cat: r,z: bih+bhh ; n_x: bih_n ; n_h: bhh_n
__global__ void build_biascat(const float* __restrict__ bih, const float* __restrict__ bhh,
                              float* __restrict__ bc) {
    int i = blockIdx.x * blockDim.x + threadIdx.x;     // [0, NG)
    if (i >= NG) return;
    float v;
    if (i < 1024)      v = bih[i] + bhh[i];
    else if (i < 1536) v = bih[i];           // bih[1024 + (i-1024)]
    else               v = bhh[i - 512];     // bhh[1024 + (i-1536)]
    bc[i] = v;
}

// ============================================================
// Split-tf32 tensor GEMM: C = act(A[M,K] @ W[N,K]^T + bias)
// B pre-split (hi/lo in global). A split on the fly (3 passes:
// Ahi*Bhi + Ahi*Blo + Alo*Bhi => ~fp32 accuracy).
// BM=128, BN=64, BK=16, 256 threads (8 warps 4x2), warp tile 32x32.
// grid = (N/64, M/128).
// A source split at k=ksplit: k<ksplit reads A2 (ld lda2), else A (ld lda,
// k offset -ksplit). ksplit must be a multiple of 16 (0 = A only).
// ACT: 0=none,1=tanh. SCATTER: row m=(t-1)*BB+b -> C[b][t][n].
// ============================================================
template <int ACT, int SCATTER>
__global__ void __launch_bounds__(256)
mma_gemm(const float* __restrict__ Ap, long lda,
         const float* __restrict__ A2p, long lda2, int ksplit,
         const uint32_t* __restrict__ Bhi, const uint32_t* __restrict__ Blo, int K,
         const float* __restrict__ bias,
         float* __restrict__ Cp, long ldc)
{
    __shared__ uint32_t Ah[128 * 20];
    __shared__ uint32_t Al[128 * 20];
    __shared__ uint32_t Bh[64 * 20];
    __shared__ uint32_t Bl[64 * 20];

    const int tid  = threadIdx.x;
    const int lane = tid & 31;
    const int w    = tid >> 5;
    const int wm   = w >> 1;          // 0..3
    const int wn   = w & 1;           // 0..1
    const int qr   = lane >> 2;       // 0..7
    const int qc   = lane & 3;        // 0..3

    const long m0 = (long)blockIdx.y * 128;
    const int  n0 = blockIdx.x * 64;

    const int arow = tid >> 1;            // 0..127
    const int acol = (tid & 1) * 8;       // 0 or 8
    const int brow = tid >> 2;            // 0..63
    const int bcol = (tid & 3) * 4;       // 0..12

    float acc[2][4][4];
#pragma unroll
    for (int mi = 0; mi < 2; ++mi)
#pragma unroll
        for (int ni = 0; ni < 4; ++ni)
#pragma unroll
            for (int j = 0; j < 4; ++j) acc[mi][ni][j] = 0.0f;

    for (int k0 = 0; k0 < K; k0 += 16) {
        const float* ap; long al; int kk0;
        if (k0 < ksplit) { ap = A2p; al = lda2; kk0 = k0; }
        else             { ap = Ap;  al = lda;  kk0 = k0 - ksplit; }
        float4 a0v = *(const float4*)(ap + (m0 + arow) * al + kk0 + acol);
        float4 a1v = *(const float4*)(ap + (m0 + arow) * al + kk0 + acol + 4);
        uint4 bhv = *(const uint4*)(Bhi + (long)(n0 + brow) * K + k0 + bcol);
        uint4 blv = *(const uint4*)(Blo + (long)(n0 + brow) * K + k0 + bcol);
        __syncthreads();
        {
            uint32_t h, l;
            uint32_t* ah = Ah + arow * 20 + acol;
            uint32_t* al_ = Al + arow * 20 + acol;
            split_tf32(a0v.x, h, l); ah[0] = h; al_[0] = l;
            split_tf32(a0v.y, h, l); ah[1] = h; al_[1] = l;
            split_tf32(a0v.z, h, l); ah[2] = h; al_[2] = l;
            split_tf32(a0v.w, h, l); ah[3] = h; al_[3] = l;
            split_tf32(a1v.x, h, l); ah[4] = h; al_[4] = l;
            split_tf32(a1v.y, h, l); ah[5] = h; al_[5] = l;
            split_tf32(a1v.z, h, l); ah[6] = h; al_[6] = l;
            split_tf32(a1v.w, h, l); ah[7] = h; al_[7] = l;
            uint32_t* bh = Bh + brow * 20 + bcol;
            uint32_t* bl = Bl + brow * 20 + bcol;
            bh[0] = bhv.x; bh[1] = bhv.y; bh[2] = bhv.z; bh[3] = bhv.w;
            bl[0] = blv.x; bl[1] = blv.y; bl[2] = blv.z; bl[3] = blv.w;
        }
        __syncthreads();

#pragma unroll
        for (int kk8 = 0; kk8 < 2; ++kk8) {
            const int kk = kk8 * 8;
            uint32_t ahf[2][4], alf[2][4];
#pragma unroll
            for (int mi = 0; mi < 2; ++mi) {
                int mrow = wm * 32 + mi * 16 + qr;
                ahf[mi][0] = Ah[mrow * 20 + kk + qc];
                ahf[mi][1] = Ah[(mrow + 8) * 20 + kk + qc];
                ahf[mi][2] = Ah[mrow * 20 + kk + qc + 4];
                ahf[mi][3] = Ah[(mrow + 8) * 20 + kk + qc + 4];
                alf[mi][0] = Al[mrow * 20 + kk + qc];
                alf[mi][1] = Al[(mrow + 8) * 20 + kk + qc];
                alf[mi][2] = Al[mrow * 20 + kk + qc + 4];
                alf[mi][3] = Al[(mrow + 8) * 20 + kk + qc + 4];
            }
#pragma unroll
            for (int ni = 0; ni < 4; ++ni) {
                int ncol = wn * 32 + ni * 8 + qr;
                uint32_t bh0 = Bh[ncol * 20 + kk + qc];
                uint32_t bh1 = Bh[ncol * 20 + kk + qc + 4];
                uint32_t bl0 = Bl[ncol * 20 + kk + qc];
                uint32_t bl1 = Bl[ncol * 20 + kk + qc + 4];
#pragma unroll
                for (int mi = 0; mi < 2; ++mi) {
                    mma8(acc[mi][ni], ahf[mi], bh0, bh1);
                    mma8(acc[mi][ni], ahf[mi], bl0, bl1);
                    mma8(acc[mi][ni], alf[mi], bh0, bh1);
                }
            }
        }
    }

    // epilogue
#pragma unroll
    for (int mi = 0; mi < 2; ++mi) {
#pragma unroll
        for (int ni = 0; ni < 4; ++ni) {
            int rloc = wm * 32 + mi * 16 + qr;
            int col  = n0 + wn * 32 + ni * 8 + qc * 2;
#pragma unroll
            for (int half = 0; half < 2; ++half) {
                long row = m0 + rloc + half * 8;
                float v0 = acc[mi][ni][half * 2 + 0] + bias[col];
                float v1 = acc[mi][ni][half * 2 + 1] + bias[col + 1];
                if (ACT == 1) { v0 = tanhf(v0); v1 = tanhf(v1); }
                if (SCATTER) {
                    long t = (row >> 12) + 1;
                    long b = row & 4095;
                    float* p = Cp + b * (LL * AA) + t * AA + col;
                    p[0] = v0; p[1] = v1;
                } else {
                    float* p = Cp + row * ldc + col;
                    p[0] = v0; p[1] = v1;
                }
            }
        }
    }
}

// ============================================================
// GRU pointwise fuse: gates [B][2048] = [r|z|n_x|n_h] (pre-act,
// biases already added) -> h_new
// ============================================================
__global__ void __launch_bounds__(256)
gru_fuse(const float* __restrict__ gates, const float* __restrict__ hprev,
         float* __restrict__ hnew)
{
    int i = blockIdx.x * blockDim.x + threadIdx.x;     // [0, BB*HH/4)
    int b  = i >> 7;              // / 128
    int n4 = (i & 127) * 4;
    const float* g = gates + (size_t)b * NG;
    float4 r4  = *(const float4*)(g + n4);
    float4 z4  = *(const float4*)(g + 512 + n4);
    float4 nx4 = *(const float4*)(g + 1024 + n4);
    float4 nh4 = *(const float4*)(g + 1536 + n4);
    float4 hp  = *(const float4*)(hprev + (size_t)b * HH + n4);
    float4 o;
    {
        float r = 1.0f / (1.0f + expf(-r4.x));
        float z = 1.0f / (1.0f + expf(-z4.x));
        float n = tanhf(nx4.x + r * nh4.x);
        o.x = (1.0f - z) * n + z * hp.x;
    }
    {
        float r = 1.0f / (1.0f + expf(-r4.y));
        float z = 1.0f / (1.0f + expf(-z4.y));
        float n = tanhf(nx4.y + r * nh4.y);
        o.y = (1.0f - z) * n + z * hp.y;
    }
    {
        float r = 1.0f / (1.0f + expf(-r4.z));
        float z = 1.0f / (1.0f + expf(-z4.z));
        float n = tanhf(nx4.z + r * nh4.z);
        o.z = (1.0f - z) * n + z * hp.z;
    }
    {
        float r = 1.0f / (1.0f + expf(-r4.w));
        float z = 1.0f / (1.0f + expf(-z4.w));
        float n = tanhf(nx4.w + r * nh4.w);
        o.w = (1.0f - z) * n + z * hp.w;
    }
    *(float4*)(hnew + (size_t)b * HH + n4) = o;
}

// ============================================================
// Orchestration
// ============================================================
extern "C" void kernel_launch(void* const* d_in, const int* in_sizes, int n_in,
                              void* d_out, int out_size)
{
    const float* latent = (const float*)d_in[0];
    const float* target = (const float*)d_in[1];
    const float* Wd1 = (const float*)d_in[2];
    const float* bd1 = (const float*)d_in[3];
    const float* Wd2 = (const float*)d_in[4];
    const float* bd2 = (const float*)d_in[5];
    const float* Wd3 = (const float*)d_in[6];
    const float* bd3 = (const float*)d_in[7];
    const float* Wih = (const float*)d_in[8];
    const float* Whh = (const float*)d_in[9];
    const float* bih = (const float*)d_in[10];
    const float* bhh = (const float*)d_in[11];
    const float* Wm1 = (const float*)d_in[12];
    const float* bm1 = (const float*)d_in[13];
    const float* Wm2 = (const float*)d_in[14];
    const float* bm2 = (const float*)d_in[15];
    const float* Wm3 = (const float*)d_in[16];
    const float* bm3 = (const float*)d_in[17];
    float* out = (float*)d_out;

    float *Hall, *P1, *P2, *gates, *xbos, *t1, *t2, *biascat;
    uint32_t *Wcat_hi, *Wcat_lo;
    uint32_t *Wd1h, *Wd1l, *Wd2h, *Wd2l, *Wd3h, *Wd3l;
    uint32_t *Wm1h, *Wm1l, *Wm2h, *Wm2l, *Wm3h, *Wm3l;
    cudaGetSymbolAddress((void**)&Hall, g_Hall);
    cudaGetSymbolAddress((void**)&P1, g_P1);
    cudaGetSymbolAddress((void**)&P2, g_P2);
    cudaGetSymbolAddress((void**)&gates, g_gates);
    cudaGetSymbolAddress((void**)&xbos, g_xbos);
    cudaGetSymbolAddress((void**)&t1, g_t1);
    cudaGetSymbolAddress((void**)&t2, g_t2);
    cudaGetSymbolAddress((void**)&biascat, g_biascat);
    cudaGetSymbolAddress((void**)&Wcat_hi, g_Wcat_hi);
    cudaGetSymbolAddress((void**)&Wcat_lo, g_Wcat_lo);
    cudaGetSymbolAddress((void**)&Wd1h, g_Wd1_hi); cudaGetSymbolAddress((void**)&Wd1l, g_Wd1_lo);
    cudaGetSymbolAddress((void**)&Wd2h, g_Wd2_hi); cudaGetSymbolAddress((void**)&Wd2l, g_Wd2_lo);
    cudaGetSymbolAddress((void**)&Wd3h, g_Wd3_hi); cudaGetSymbolAddress((void**)&Wd3l, g_Wd3_lo);
    cudaGetSymbolAddress((void**)&Wm1h, g_Wm1_hi); cudaGetSymbolAddress((void**)&Wm1l, g_Wm1_lo);
    cudaGetSymbolAddress((void**)&Wm2h, g_Wm2_hi); cudaGetSymbolAddress((void**)&Wm2l, g_Wm2_lo);
    cudaGetSymbolAddress((void**)&Wm3h, g_Wm3_hi); cudaGetSymbolAddress((void**)&Wm3l, g_Wm3_lo);

    const long M2 = (long)(LL - 1) * BB;  // 520192

    // ---- setup ----
    fill_bos_out<<<(BB * AA) / 256, 256>>>(out);
    fill_xbos<<<(BB * AA) / 256, 256>>>(xbos);
    build_wcat<<<(NG * KG + 255) / 256, 256>>>(Wih, Whh, Wcat_hi, Wcat_lo);
    build_biascat<<<(NG + 255) / 256, 256>>>(bih, bhh, biascat);
    split_w<<<(HH * LAT + 255) / 256, 256>>>(Wd1, Wd1h, Wd1l, HH * LAT);
    split_w<<<(HH * HH + 255) / 256, 256>>>(Wd2, Wd2h, Wd2l, HH * HH);
    split_w<<<(HH * HH + 255) / 256, 256>>>(Wd3, Wd3h, Wd3l, HH * HH);
    split_w<<<(HH * HH + 255) / 256, 256>>>(Wm1, Wm1h, Wm1l, HH * HH);
    split_w<<<(AA * HH + 255) / 256, 256>>>(Wm2, Wm2h, Wm2l, AA * HH);
    split_w<<<(AA * AA + 255) / 256, 256>>>(Wm3, Wm3h, Wm3l, AA * AA);

    // ---- h0 = Wd3(tanh(Wd2(tanh(Wd1(latent))))) ----
    mma_gemm<1, 0><<<dim3(HH / 64, BB / 128), 256>>>(latent, LAT, nullptr, 0, 0, Wd1h, Wd1l, LAT, bd1, t1, HH);
    mma_gemm<1, 0><<<dim3(HH / 64, BB / 128), 256>>>(t1, HH, nullptr, 0, 0, Wd2h, Wd2l, HH, bd2, t2, HH);
    mma_gemm<0, 0><<<dim3(HH / 64, BB / 128), 256>>>(t2, HH, nullptr, 0, 0, Wd3h, Wd3l, HH, bd3, Hall, HH);

    // ---- sequential GRU ----
    for (int t = 1; t < LL; ++t) {
        const float* x;
        long ldx;
        if (t == 1) { x = xbos; ldx = AA; }
        else        { x = target + (size_t)(t - 1) * AA; ldx = (long)LL * AA; }
        const float* hprev = Hall + (size_t)(t - 1) * BB * HH;
        // gates = [x|h] @ Wcat2^T + biascat   (K = 576, N = 2048)
        mma_gemm<0, 0><<<dim3(NG / 64, BB / 128), 256>>>(
            hprev, HH, x, ldx, AA, Wcat_hi, Wcat_lo, KG, biascat, gates, NG);
        gru_fuse<<<(BB * HH / 4) / 256, 256>>>(gates, hprev,
                                               Hall + (size_t)t * BB * HH);
    }

    // ---- per-step decoder over all 127 steps at once ----
    mma_gemm<1, 0><<<dim3(HH / 64, M2 / 128), 256>>>(Hall + (size_t)BB * HH, HH, nullptr, 0, 0, Wm1h, Wm1l, HH, bm1, P1, HH);
    mma_gemm<1, 0><<<dim3(AA / 64, M2 / 128), 256>>>(P1, HH, nullptr, 0, 0, Wm2h, Wm2l, HH, bm2, P2, AA);
    mma_gemm<0, 1><<<dim3(AA / 64, M2 / 128), 256>>>(P2, AA, nullptr, 0, 0, Wm3h, Wm3l, AA, bm3, out, 0);
}

// round 6
// speedup vs baseline: 1.8184x; 1.8184x over previous
#include <cuda_runtime.h>
#include <cuda_bf16.h>
#include <math.h>
#include <stdint.h>

#define BB 4096
#define LAT 256
#define HH 512
#define AA 64
#define LL 128
#define NGT 2048         // gate gemm N: interleaved [r,z,nx,nh] per hidden j
#define KGT 576          // gate gemm K: [x(64) | h(512)]

typedef __nv_bfloat16 bf16;

// ---- scratch (static device globals; ~2.4 GB, under aarch64 reloc limit) ----
__device__ bf16  g_Hdhi[(size_t)(LL - 1) * BB * HH];   // h_t hi, slots t=1..127
__device__ bf16  g_Hdlo[(size_t)(LL - 1) * BB * HH];
__device__ bf16  g_P1hi[(size_t)(LL - 1) * BB * HH];
__device__ bf16  g_P1lo[(size_t)(LL - 1) * BB * HH];
__device__ bf16  g_P2hi[(size_t)(LL - 1) * BB * AA];
__device__ bf16  g_P2lo[(size_t)(LL - 1) * BB * AA];
__device__ bf16  g_Xhi[(size_t)(LL - 1) * BB * AA];
__device__ bf16  g_Xlo[(size_t)(LL - 1) * BB * AA];
__device__ float g_h32a[(size_t)BB * HH];
__device__ float g_h32b[(size_t)BB * HH];
__device__ bf16  g_H0hi[(size_t)BB * HH], g_H0lo[(size_t)BB * HH];
__device__ bf16  g_t1hi[(size_t)BB * HH], g_t1lo[(size_t)BB * HH];
__device__ bf16  g_t2hi[(size_t)BB * HH], g_t2lo[(size_t)BB * HH];
__device__ bf16  g_Lhi[(size_t)BB * LAT], g_Llo[(size_t)BB * LAT];
__device__ bf16  g_Wcathi[(size_t)NGT * KGT], g_Wcatlo[(size_t)NGT * KGT];
__device__ bf16  g_Wd1hi[HH * LAT], g_Wd1lo[HH * LAT];
__device__ bf16  g_Wd2hi[HH * HH],  g_Wd2lo[HH * HH];
__device__ bf16  g_Wd3hi[HH * HH],  g_Wd3lo[HH * HH];
__device__ bf16  g_Wm1hi[HH * HH],  g_Wm1lo[HH * HH];
__device__ bf16  g_Wm2hi[AA * HH],  g_Wm2lo[AA * HH];
__device__ bf16  g_Wm3hi[AA * AA],  g_Wm3lo[AA * AA];
__device__ float g_biascat[NGT];

// ============================================================
// helpers
// ============================================================
__device__ __forceinline__ uint32_t smem_u32(const void* p) {
    uint32_t a;
    asm("{ .reg .u64 t; cvta.to.shared.u64 t, %1; cvt.u32.u64 %0, t; }" : "=r"(a) : "l"(p));
    return a;
}
__device__ __forceinline__ void cpa16(uint32_t dst, const void* src) {
    asm volatile("cp.async.cg.shared.global [%0], [%1], 16;" :: "r"(dst), "l"(src));
}
__device__ __forceinline__ void cpa_commit() {
    asm volatile("cp.async.commit_group;" ::: "memory");
}
__device__ __forceinline__ void cpa_wait1() {
    asm volatile("cp.async.wait_group 1;" ::: "memory");
}
__device__ __forceinline__ void bsplit(float v, bf16& hi, bf16& lo) {
    hi = __float2bfloat16_rn(v);
    lo = __float2bfloat16_rn(v - __bfloat162float(hi));
}
__device__ __forceinline__ uint32_t pack2(float a, float b) {
    __nv_bfloat162 t = __floats2bfloat162_rn(a, b);
    return *(uint32_t*)&t;
}
__device__ __forceinline__ float sigf(float x) { return 1.0f / (1.0f + expf(-x)); }

__device__ __forceinline__ void mma16(float d[4], const uint32_t a[4], const uint32_t b[2]) {
    asm volatile(
        "mma.sync.aligned.m16n8k16.row.col.f32.bf16.bf16.f32 "
        "{%0,%1,%2,%3},{%4,%5,%6,%7},{%8,%9},{%0,%1,%2,%3};"
        : "+f"(d[0]), "+f"(d[1]), "+f"(d[2]), "+f"(d[3])
        : "r"(a[0]), "r"(a[1]), "r"(a[2]), "r"(a[3]), "r"(b[0]), "r"(b[1]));
}

// ============================================================
// Setup kernels
// ============================================================
__global__ void fill_bos_out(float* __restrict__ out) {
    int idx = blockIdx.x * blockDim.x + threadIdx.x;   // [0, BB*AA)
    int b = idx >> 6, a = idx & 63;
    out[(size_t)b * (LL * AA) + a] = (a == 0) ? 16.0f : -16.0f;
}
// X[(t-1)*BB + b][a] : t=1 -> bos ; t>=2 -> target[b][t-1][a]
__global__ void build_X(const float* __restrict__ target,
                        bf16* __restrict__ xhi, bf16* __restrict__ xlo) {
    size_t idx = (size_t)blockIdx.x * blockDim.x + threadIdx.x;
    int a = (int)(idx & 63);
    size_t row = idx >> 6;
    int trow = (int)(row >> 12);
    int b = (int)(row & 4095);
    float v;
    if (trow == 0) v = (a == 0) ? 16.0f : -16.0f;
    else           v = target[((size_t)b << 13) + (size_t)trow * AA + a];
    bf16 h, l; bsplit(v, h, l);
    xhi[idx] = h; xlo[idx] = l;
}
__global__ void split_bf(const float* __restrict__ src, bf16* __restrict__ hi,
                         bf16* __restrict__ lo, int n) {
    int i = blockIdx.x * blockDim.x + threadIdx.x;
    if (i < n) { bf16 h, l; bsplit(src[i], h, l); hi[i] = h; lo[i] = l; }
}
// interleaved gate rows: row 4j+g, g in {0:r, 1:z, 2:nx, 3:nh}
// k<64 -> Wih column, else Whh column (nx has 0 h-part, nh has 0 x-part)
__global__ void build_wcat(const float* __restrict__ Wih, const float* __restrict__ Whh,
                           bf16* __restrict__ hi, bf16* __restrict__ lo) {
    int i = blockIdx.x * blockDim.x + threadIdx.x;     // [0, NGT*KGT)
    if (i >= NGT * KGT) return;
    int k = i % KGT, row = i / KGT;
    int j = row >> 2, gg = row & 3;
    float v;
    if (gg == 0)      v = (k < AA) ? Wih[j * AA + k]          : Whh[(size_t)j * HH + k - AA];
    else if (gg == 1) v = (k < AA) ? Wih[(512 + j) * AA + k]  : Whh[(size_t)(512 + j) * HH + k - AA];
    else if (gg == 2) v = (k < AA) ? Wih[(1024 + j) * AA + k] : 0.0f;
    else              v = (k < AA) ? 0.0f                      : Whh[(size_t)(1024 + j) * HH + k - AA];
    bf16 h, l; bsplit(v, h, l);
    hi[i] = h; lo[i] = l;
}
__global__ void build_biascat(const float* __restrict__ bih, const float* __restrict__ bhh,
                              float* __restrict__ bc) {
    int i = blockIdx.x * blockDim.x + threadIdx.x;
    if (i >= NGT) return;
    int j = i >> 2, gg = i & 3;
    float v;
    if (gg == 0)      v = bih[j] + bhh[j];
    else if (gg == 1) v = bih[512 + j] + bhh[512 + j];
    else if (gg == 2) v = bih[1024 + j];
    else              v = bhh[1024 + j];
    bc[i] = v;
}

// ============================================================
// bf16 split-3 mma GEMM: C = epi(A[M,K] @ W[N,K]^T + bias)
// A,B as bf16 hi/lo; acc += Ahi*Bhi + Ahi*Blo + Alo*Bhi (fp32 acc).
// BM=128, BN in {128,64}, BK=32, 256 threads, cp.async double buffer.
// A split at ksplit (k<ksplit -> X pointers).
// EPI: 1 = tanh -> bf16 hi/lo; 2 = f32 + bf16 hi/lo;
//      3 = scatter f32 out[b][t][n]; 4 = fused GRU gate epilogue.
// ============================================================
template <int BN, int EPI>
__global__ void __launch_bounds__(256)
mma_gemm(const bf16* __restrict__ Ahi, const bf16* __restrict__ Alo, long lda,
         const bf16* __restrict__ Xhi, const bf16* __restrict__ Xlo, long ldx, int ksplit,
         const bf16* __restrict__ Bhi_g, const bf16* __restrict__ Blo_g, int K,
         const float* __restrict__ bias,
         float* __restrict__ Cf, long ldc,
         bf16* __restrict__ Chi, bf16* __restrict__ Clo,
         const float* __restrict__ hprev32, float* __restrict__ hnew32)
{
    constexpr int SS = 40;                      // smem row stride (bf16), conflict-free
    constexpr int WARPS_M = (BN == 128) ? 2 : 4;
    constexpr int WM = 128 / WARPS_M;           // 64 or 32
    constexpr int MI = WM / 16;                 // 4 or 2
    constexpr int NI = 4;                       // warp N tile = 32
    constexpr int ABYT = 128 * SS * 2;          // 10240 B per A part
    constexpr int BBYT = BN * SS * 2;
    constexpr int BUF = 2 * ABYT + 2 * BBYT;

    extern __shared__ char smem[];
    const uint32_t sb = smem_u32(smem);

    const int tid = threadIdx.x;
    const int wid = tid >> 5, lane = tid & 31;
    const int wm = wid % WARPS_M, wn = wid / WARPS_M;
    const int gr = lane >> 2, tq = lane & 3;

    const long m0 = (long)blockIdx.y * 128;
    const int  n0 = blockIdx.x * BN;
    const int  nc = K >> 5;

    float acc[MI][NI][4];
#pragma unroll
    for (int mi = 0; mi < MI; ++mi)
#pragma unroll
        for (int ni = 0; ni < NI; ++ni)
#pragma unroll
            for (int q = 0; q < 4; ++q) acc[mi][ni][q] = 0.0f;

    auto load_chunk = [&](int ch) {
        const int k0 = ch << 5;
        const bf16 *ah, *al; long ld, kk;
        if (k0 < ksplit) { ah = Xhi; al = Xlo; ld = ldx; kk = k0; }
        else             { ah = Ahi; al = Alo; ld = lda; kk = k0 - ksplit; }
        const uint32_t base = sb + (ch & 1) * BUF;
#pragma unroll
        for (int it = 0; it < 2; ++it) {
            int e = tid + it * 256;
            int row = e >> 2, seg = e & 3;
            long go = (m0 + row) * ld + kk + seg * 8;
            uint32_t d = base + (uint32_t)(row * SS + seg * 8) * 2;
            cpa16(d, ah + go);
            cpa16(d + ABYT, al + go);
        }
#pragma unroll
        for (int it = 0; it < BN / 64; ++it) {
            int e = tid + it * 256;
            int row = e >> 2, seg = e & 3;
            long go = (long)(n0 + row) * K + k0 + seg * 8;
            uint32_t d = base + 2 * ABYT + (uint32_t)(row * SS + seg * 8) * 2;
            cpa16(d, Bhi_g + go);
            cpa16(d + BBYT, Blo_g + go);
        }
    };

    load_chunk(0);
    cpa_commit();

    for (int ch = 0; ch < nc; ++ch) {
        if (ch > 0) __syncthreads();            // compute(ch-1) done before overwriting its buf
        if (ch + 1 < nc) load_chunk(ch + 1);
        cpa_commit();
        cpa_wait1();                            // load(ch) complete
        __syncthreads();

        const bf16* As_hi = (const bf16*)(smem + (ch & 1) * BUF);
        const bf16* As_lo = (const bf16*)((const char*)As_hi + ABYT);
        const bf16* Bs_hi = (const bf16*)((const char*)As_hi + 2 * ABYT);
        const bf16* Bs_lo = (const bf16*)((const char*)Bs_hi + BBYT);

#pragma unroll
        for (int k16 = 0; k16 < 2; ++k16) {
            const int kk = k16 * 16 + 2 * tq;
            uint32_t ah[MI][4], al_[MI][4], bh[NI][2], bl[NI][2];
#pragma unroll
            for (int mi = 0; mi < MI; ++mi) {
                int r0 = wm * WM + mi * 16 + gr;
                ah[mi][0]  = *(const uint32_t*)(As_hi + r0 * SS + kk);
                ah[mi][1]  = *(const uint32_t*)(As_hi + (r0 + 8) * SS + kk);
                ah[mi][2]  = *(const uint32_t*)(As_hi + r0 * SS + kk + 8);
                ah[mi][3]  = *(const uint32_t*)(As_hi + (r0 + 8) * SS + kk + 8);
                al_[mi][0] = *(const uint32_t*)(As_lo + r0 * SS + kk);
                al_[mi][1] = *(const uint32_t*)(As_lo + (r0 + 8) * SS + kk);
                al_[mi][2] = *(const uint32_t*)(As_lo + r0 * SS + kk + 8);
                al_[mi][3] = *(const uint32_t*)(As_lo + (r0 + 8) * SS + kk + 8);
            }
#pragma unroll
            for (int ni = 0; ni < NI; ++ni) {
                int nn = wn * 32 + ni * 8 + gr;
                bh[ni][0] = *(const uint32_t*)(Bs_hi + nn * SS + kk);
                bh[ni][1] = *(const uint32_t*)(Bs_hi + nn * SS + kk + 8);
                bl[ni][0] = *(const uint32_t*)(Bs_lo + nn * SS + kk);
                bl[ni][1] = *(const uint32_t*)(Bs_lo + nn * SS + kk + 8);
            }
#pragma unroll
            for (int mi = 0; mi < MI; ++mi)
#pragma unroll
                for (int ni = 0; ni < NI; ++ni) {
                    mma16(acc[mi][ni], ah[mi], bh[ni]);
                    mma16(acc[mi][ni], ah[mi], bl[ni]);
                    mma16(acc[mi][ni], al_[mi], bh[ni]);
                }
        }
    }

    // ---- epilogue ----
#pragma unroll
    for (int mi = 0; mi < MI; ++mi) {
#pragma unroll
        for (int ni = 0; ni < NI; ++ni) {
            const int col = n0 + wn * 32 + ni * 8 + 2 * tq;
            const long mA = m0 + wm * WM + mi * 16 + gr;      // rows gr / gr+8
            float2 bc = *(const float2*)(bias + col);
            float v0 = acc[mi][ni][0] + bc.x;
            float v1 = acc[mi][ni][1] + bc.y;
            float v2 = acc[mi][ni][2] + bc.x;
            float v3 = acc[mi][ni][3] + bc.y;

            if (EPI == 1 || EPI == 2) {
                if (EPI == 1) { v0 = tanhf(v0); v1 = tanhf(v1); v2 = tanhf(v2); v3 = tanhf(v3); }
                else {
                    *(float2*)(Cf + mA * ldc + col) = make_float2(v0, v1);
                    *(float2*)(Cf + (mA + 8) * ldc + col) = make_float2(v2, v3);
                }
                bf16 h0, l0, h1, l1;
                bsplit(v0, h0, l0); bsplit(v1, h1, l1);
                *(uint32_t*)(Chi + mA * ldc + col) = pack2(__bfloat162float(h0), __bfloat162float(h1));
                *(uint32_t*)(Clo + mA * ldc + col) = pack2(__bfloat162float(l0), __bfloat162float(l1));
                bsplit(v2, h0, l0); bsplit(v3, h1, l1);
                *(uint32_t*)(Chi + (mA + 8) * ldc + col) = pack2(__bfloat162float(h0), __bfloat162float(h1));
                *(uint32_t*)(Clo + (mA + 8) * ldc + col) = pack2(__bfloat162float(l0), __bfloat162float(l1));
            } else if (EPI == 3) {
                long t1_ = (mA >> 12) + 1, b1_ = mA & 4095;
                long t2_ = ((mA + 8) >> 12) + 1, b2_ = (mA + 8) & 4095;
                *(float2*)(Cf + b1_ * (LL * AA) + t1_ * AA + col) = make_float2(v0, v1);
                *(float2*)(Cf + b2_ * (LL * AA) + t2_ * AA + col) = make_float2(v2, v3);
            } else {  // EPI == 4 : fused GRU gates, interleaved [r,z,nx,nh]
                float x0 = __shfl_xor_sync(0xFFFFFFFFu, v0, 1);
                float x1 = __shfl_xor_sync(0xFFFFFFFFu, v1, 1);
                float x2 = __shfl_xor_sync(0xFFFFFFFFu, v2, 1);
                float x3 = __shfl_xor_sync(0xFFFFFFFFu, v3, 1);
                const int j = ((n0 + wn * 32 + ni * 8) >> 2) + (tq >> 1);
                const long m = mA + ((tq & 1) ? 8 : 0);
                float rr, zz, nx, nh;
                if ((tq & 1) == 0) { rr = v0; zz = v1; nx = x0; nh = x1; }
                else               { rr = x2; zz = x3; nx = v2; nh = v3; }
                float r_ = sigf(rr), z_ = sigf(zz);
                float hp = hprev32[m * HH + j];
                float hv = (1.0f - z_) * tanhf(nx + r_ * nh) + z_ * hp;
                hnew32[m * HH + j] = hv;
                bf16 hb, lb; bsplit(hv, hb, lb);
                Chi[m * HH + j] = hb;
                Clo[m * HH + j] = lb;
            }
        }
    }
}

// ============================================================
// Orchestration
// ============================================================
extern "C" void kernel_launch(void* const* d_in, const int* in_sizes, int n_in,
                              void* d_out, int out_size)
{
    const float* latent = (const float*)d_in[0];
    const float* target = (const float*)d_in[1];
    const float* Wd1 = (const float*)d_in[2];
    const float* bd1 = (const float*)d_in[3];
    const float* Wd2 = (const float*)d_in[4];
    const float* bd2 = (const float*)d_in[5];
    const float* Wd3 = (const float*)d_in[6];
    const float* bd3 = (const float*)d_in[7];
    const float* Wih = (const float*)d_in[8];
    const float* Whh = (const float*)d_in[9];
    const float* bih = (const float*)d_in[10];
    const float* bhh = (const float*)d_in[11];
    const float* Wm1 = (const float*)d_in[12];
    const float* bm1 = (const float*)d_in[13];
    const float* Wm2 = (const float*)d_in[14];
    const float* bm2 = (const float*)d_in[15];
    const float* Wm3 = (const float*)d_in[16];
    const float* bm3 = (const float*)d_in[17];
    float* out = (float*)d_out;

#define SYM(v, s) cudaGetSymbolAddress((void**)&v, s)
    bf16 *Hdhi, *Hdlo, *P1hi, *P1lo, *P2hi, *P2lo, *Xhi, *Xlo;
    bf16 *H0hi, *H0lo, *t1hi, *t1lo, *t2hi, *t2lo, *Lhi, *Llo;
    bf16 *Wcathi, *Wcatlo, *Wd1hi, *Wd1lo, *Wd2hi, *Wd2lo, *Wd3hi, *Wd3lo;
    bf16 *Wm1hi, *Wm1lo, *Wm2hi, *Wm2lo, *Wm3hi, *Wm3lo;
    float *h32a, *h32b, *biascat;
    SYM(Hdhi, g_Hdhi); SYM(Hdlo, g_Hdlo);
    SYM(P1hi, g_P1hi); SYM(P1lo, g_P1lo);
    SYM(P2hi, g_P2hi); SYM(P2lo, g_P2lo);
    SYM(Xhi, g_Xhi);   SYM(Xlo, g_Xlo);
    SYM(H0hi, g_H0hi); SYM(H0lo, g_H0lo);
    SYM(t1hi, g_t1hi); SYM(t1lo, g_t1lo);
    SYM(t2hi, g_t2hi); SYM(t2lo, g_t2lo);
    SYM(Lhi, g_Lhi);   SYM(Llo, g_Llo);
    SYM(Wcathi, g_Wcathi); SYM(Wcatlo, g_Wcatlo);
    SYM(Wd1hi, g_Wd1hi); SYM(Wd1lo, g_Wd1lo);
    SYM(Wd2hi, g_Wd2hi); SYM(Wd2lo, g_Wd2lo);
    SYM(Wd3hi, g_Wd3hi); SYM(Wd3lo, g_Wd3lo);
    SYM(Wm1hi, g_Wm1hi); SYM(Wm1lo, g_Wm1lo);
    SYM(Wm2hi, g_Wm2hi); SYM(Wm2lo, g_Wm2lo);
    SYM(Wm3hi, g_Wm3hi); SYM(Wm3lo, g_Wm3lo);
    SYM(h32a, g_h32a); SYM(h32b, g_h32b); SYM(biascat, g_biascat);
#undef SYM

    const long M2 = (long)(LL - 1) * BB;  // 520192
    constexpr int SM128 = 2 * (2 * 128 * 40 * 2 + 2 * 128 * 40 * 2);   // 81920
    constexpr int SM64  = 2 * (2 * 128 * 40 * 2 + 2 * 64 * 40 * 2);    // 61440
    cudaFuncSetAttribute(mma_gemm<128, 1>, cudaFuncAttributeMaxDynamicSharedMemorySize, SM128);
    cudaFuncSetAttribute(mma_gemm<128, 2>, cudaFuncAttributeMaxDynamicSharedMemorySize, SM128);
    cudaFuncSetAttribute(mma_gemm<128, 4>, cudaFuncAttributeMaxDynamicSharedMemorySize, SM128);
    cudaFuncSetAttribute(mma_gemm<64, 1>,  cudaFuncAttributeMaxDynamicSharedMemorySize, SM64);
    cudaFuncSetAttribute(mma_gemm<64, 3>,  cudaFuncAttributeMaxDynamicSharedMemorySize, SM64);

    // ---- setup ----
    fill_bos_out<<<(BB * AA) / 256, 256>>>(out);
    build_X<<<(int)((M2 * AA) / 256), 256>>>(target, Xhi, Xlo);
    split_bf<<<(BB * LAT + 255) / 256, 256>>>(latent, Lhi, Llo, BB * LAT);
    build_wcat<<<(NGT * KGT + 255) / 256, 256>>>(Wih, Whh, Wcathi, Wcatlo);
    build_biascat<<<(NGT + 255) / 256, 256>>>(bih, bhh, biascat);
    split_bf<<<(HH * LAT + 255) / 256, 256>>>(Wd1, Wd1hi, Wd1lo, HH * LAT);
    split_bf<<<(HH * HH + 255) / 256, 256>>>(Wd2, Wd2hi, Wd2lo, HH * HH);
    split_bf<<<(HH * HH + 255) / 256, 256>>>(Wd3, Wd3hi, Wd3lo, HH * HH);
    split_bf<<<(HH * HH + 255) / 256, 256>>>(Wm1, Wm1hi, Wm1lo, HH * HH);
    split_bf<<<(AA * HH + 255) / 256, 256>>>(Wm2, Wm2hi, Wm2lo, AA * HH);
    split_bf<<<(AA * AA + 255) / 256, 256>>>(Wm3, Wm3hi, Wm3lo, AA * AA);

    // ---- h0 = Wd3(tanh(Wd2(tanh(Wd1(latent))))) ----
    mma_gemm<128, 1><<<dim3(HH / 128, BB / 128), 256, SM128>>>(
        Lhi, Llo, LAT, nullptr, nullptr, 0, 0, Wd1hi, Wd1lo, LAT, bd1,
        nullptr, HH, t1hi, t1lo, nullptr, nullptr);
    mma_gemm<128, 1><<<dim3(HH / 128, BB / 128), 256, SM128>>>(
        t1hi, t1lo, HH, nullptr, nullptr, 0, 0, Wd2hi, Wd2lo, HH, bd2,
        nullptr, HH, t2hi, t2lo, nullptr, nullptr);
    mma_gemm<128, 2><<<dim3(HH / 128, BB / 128), 256, SM128>>>(
        t2hi, t2lo, HH, nullptr, nullptr, 0, 0, Wd3hi, Wd3lo, HH, bd3,
        h32a, HH, H0hi, H0lo, nullptr, nullptr);

    // ---- sequential GRU: one fused gemm+gate launch per step ----
    float* hp32 = h32a;
    float* hn32 = h32b;
    for (int t = 1; t < LL; ++t) {
        const bf16* hhi = (t == 1) ? H0hi : Hdhi + (size_t)(t - 2) * BB * HH;
        const bf16* hlo = (t == 1) ? H0lo : Hdlo + (size_t)(t - 2) * BB * HH;
        mma_gemm<128, 4><<<dim3(NGT / 128, BB / 128), 256, SM128>>>(
            hhi, hlo, HH,
            Xhi + (size_t)(t - 1) * BB * AA, Xlo + (size_t)(t - 1) * BB * AA, AA, AA,
            Wcathi, Wcatlo, KGT, biascat,
            nullptr, HH,
            Hdhi + (size_t)(t - 1) * BB * HH, Hdlo + (size_t)(t - 1) * BB * HH,
            hp32, hn32);
        float* tmp = hp32; hp32 = hn32; hn32 = tmp;
    }

    // ---- per-step decoder over all 127 steps at once ----
    mma_gemm<128, 1><<<dim3(HH / 128, (int)(M2 / 128)), 256, SM128>>>(
        Hdhi, Hdlo, HH, nullptr, nullptr, 0, 0, Wm1hi, Wm1lo, HH, bm1,
        nullptr, HH, P1hi, P1lo, nullptr, nullptr);
    mma_gemm<64, 1><<<dim3(1, (int)(M2 / 128)), 256, SM64>>>(
        P1hi, P1lo, HH, nullptr, nullptr, 0, 0, Wm2hi, Wm2lo, HH, bm2,
        nullptr, AA, P2hi, P2lo, nullptr, nullptr);
    mma_gemm<64, 3><<<dim3(1, (int)(M2 / 128)), 256, SM64>>>(
        P2hi, P2lo, AA, nullptr, nullptr, 0, 0, Wm3hi, Wm3lo, AA, bm3,
        out, 0, nullptr, nullptr, nullptr, nullptr);
}

// round 7
// speedup vs baseline: 2.4405x; 1.3421x over previous
#include <cuda_runtime.h>
#include <cuda_fp16.h>
#include <math.h>
#include <stdint.h>

#define BB 4096
#define LAT 256
#define HH 512
#define AA 64
#define LL 128
#define NGT 2048         // gate gemm N: interleaved [r,z,nx,nh] per hidden j
#define KGT 576          // gate gemm K: [x(64) | h(512)]

// ---- scratch (static device globals; ~1.25 GB) ----
__device__ half  g_Hd[(size_t)(LL - 1) * BB * HH];     // h_t fp16, slots t=1..127
__device__ half  g_P1[(size_t)(LL - 1) * BB * HH];
__device__ half  g_P2[(size_t)(LL - 1) * BB * AA];
__device__ half  g_X[(size_t)(LL - 1) * BB * AA];
__device__ float g_h32a[(size_t)BB * HH];
__device__ float g_h32b[(size_t)BB * HH];
__device__ half  g_H0[(size_t)BB * HH];
__device__ half  g_t1[(size_t)BB * HH];
__device__ half  g_t2[(size_t)BB * HH];
__device__ half  g_L[(size_t)BB * LAT];
__device__ half  g_Wcathi[(size_t)NGT * KGT], g_Wcatlo[(size_t)NGT * KGT];
__device__ half  g_Wd1hi[HH * LAT], g_Wd1lo[HH * LAT];
__device__ half  g_Wd2hi[HH * HH],  g_Wd2lo[HH * HH];
__device__ half  g_Wd3hi[HH * HH],  g_Wd3lo[HH * HH];
__device__ half  g_Wm1hi[HH * HH],  g_Wm1lo[HH * HH];
__device__ half  g_Wm2hi[AA * HH],  g_Wm2lo[AA * HH];
__device__ half  g_Wm3hi[AA * AA],  g_Wm3lo[AA * AA];
__device__ float g_biascat[NGT];

// ============================================================
// helpers
// ============================================================
__device__ __forceinline__ uint32_t smem_u32(const void* p) {
    uint32_t a;
    asm("{ .reg .u64 t; cvta.to.shared.u64 t, %1; cvt.u32.u64 %0, t; }" : "=r"(a) : "l"(p));
    return a;
}
__device__ __forceinline__ void cpa16(uint32_t dst, const void* src) {
    asm volatile("cp.async.cg.shared.global [%0], [%1], 16;" :: "r"(dst), "l"(src));
}
__device__ __forceinline__ void cpa_commit() {
    asm volatile("cp.async.commit_group;" ::: "memory");
}
__device__ __forceinline__ void cpa_wait1() {
    asm volatile("cp.async.wait_group 1;" ::: "memory");
}
__device__ __forceinline__ void hsplit(float v, half& hi, half& lo) {
    hi = __float2half_rn(v);
    lo = __float2half_rn(v - __half2float(hi));
}
__device__ __forceinline__ float sigf(float x) { return 1.0f / (1.0f + expf(-x)); }

__device__ __forceinline__ void mma16(float d[4], const uint32_t a[4], const uint32_t b[2]) {
    asm volatile(
        "mma.sync.aligned.m16n8k16.row.col.f32.f16.f16.f32 "
        "{%0,%1,%2,%3},{%4,%5,%6,%7},{%8,%9},{%0,%1,%2,%3};"
        : "+f"(d[0]), "+f"(d[1]), "+f"(d[2]), "+f"(d[3])
        : "r"(a[0]), "r"(a[1]), "r"(a[2]), "r"(a[3]), "r"(b[0]), "r"(b[1]));
}

// ============================================================
// Setup kernels
// ============================================================
__global__ void fill_bos_out(float* __restrict__ out) {
    int idx = blockIdx.x * blockDim.x + threadIdx.x;   // [0, BB*AA)
    int b = idx >> 6, a = idx & 63;
    out[(size_t)b * (LL * AA) + a] = (a == 0) ? 16.0f : -16.0f;
}
// X[(t-1)*BB + b][a] : t=1 -> bos ; t>=2 -> target[b][t-1][a]
__global__ void build_X(const float* __restrict__ target, half* __restrict__ X) {
    size_t idx = (size_t)blockIdx.x * blockDim.x + threadIdx.x;
    int a = (int)(idx & 63);
    size_t row = idx >> 6;
    int trow = (int)(row >> 12);
    int b = (int)(row & 4095);
    float v;
    if (trow == 0) v = (a == 0) ? 16.0f : -16.0f;
    else           v = target[((size_t)b << 13) + (size_t)trow * AA + a];
    X[idx] = __float2half_rn(v);
}
__global__ void tohalf(const float* __restrict__ src, half* __restrict__ dst, int n) {
    int i = blockIdx.x * blockDim.x + threadIdx.x;
    if (i < n) dst[i] = __float2half_rn(src[i]);
}
__global__ void split_h(const float* __restrict__ src, half* __restrict__ hi,
                        half* __restrict__ lo, int n) {
    int i = blockIdx.x * blockDim.x + threadIdx.x;
    if (i < n) { half h, l; hsplit(src[i], h, l); hi[i] = h; lo[i] = l; }
}
// interleaved gate rows: row 4j+g, g in {0:r, 1:z, 2:nx, 3:nh}
__global__ void build_wcat(const float* __restrict__ Wih, const float* __restrict__ Whh,
                           half* __restrict__ hi, half* __restrict__ lo) {
    int i = blockIdx.x * blockDim.x + threadIdx.x;     // [0, NGT*KGT)
    if (i >= NGT * KGT) return;
    int k = i % KGT, row = i / KGT;
    int j = row >> 2, gg = row & 3;
    float v;
    if (gg == 0)      v = (k < AA) ? Wih[j * AA + k]          : Whh[(size_t)j * HH + k - AA];
    else if (gg == 1) v = (k < AA) ? Wih[(512 + j) * AA + k]  : Whh[(size_t)(512 + j) * HH + k - AA];
    else if (gg == 2) v = (k < AA) ? Wih[(1024 + j) * AA + k] : 0.0f;
    else              v = (k < AA) ? 0.0f                      : Whh[(size_t)(1024 + j) * HH + k - AA];
    half h, l; hsplit(v, h, l);
    hi[i] = h; lo[i] = l;
}
__global__ void build_biascat(const float* __restrict__ bih, const float* __restrict__ bhh,
                              float* __restrict__ bc) {
    int i = blockIdx.x * blockDim.x + threadIdx.x;
    if (i >= NGT) return;
    int j = i >> 2, gg = i & 3;
    float v;
    if (gg == 0)      v = bih[j] + bhh[j];
    else if (gg == 1) v = bih[512 + j] + bhh[512 + j];
    else if (gg == 2) v = bih[1024 + j];
    else              v = bhh[1024 + j];
    bc[i] = v;
}

// ============================================================
// fp16 2-term split GEMM: C = epi(A[M,K] @ W[N,K]^T + bias)
// A single fp16; B hi/lo fp16. acc += A*Bhi + A*Blo (fp32 acc) ==
// exact A x fp32-grade W; error only from fp16(A) quantization.
// BM=128, BN in {128,64}, BK=32, 256 threads, cp.async double buffer.
// A source split at ksplit (k<ksplit -> X pointer).
// EPI: 1 = tanh -> fp16; 2 = f32 + fp16; 3 = scatter f32 out[b][t][n];
//      4 = fused GRU gate epilogue (interleaved [r,z,nx,nh]).
// ============================================================
template <int BN, int EPI>
__global__ void __launch_bounds__(256)
mma_gemm(const half* __restrict__ A_g, long lda,
         const half* __restrict__ X_g, long ldx, int ksplit,
         const half* __restrict__ Bhi_g, const half* __restrict__ Blo_g, int K,
         const float* __restrict__ bias,
         float* __restrict__ Cf, long ldc,
         half* __restrict__ Ch,
         const float* __restrict__ hprev32, float* __restrict__ hnew32)
{
    constexpr int SS = 40;                      // smem row stride (halfs)
    constexpr int WARPS_M = (BN == 128) ? 2 : 4;
    constexpr int WM = 128 / WARPS_M;           // 64 or 32
    constexpr int MI = WM / 16;                 // 4 or 2
    constexpr int NI = 4;                       // warp N tile = 32
    constexpr int ABYT = 128 * SS * 2;          // 10240 B
    constexpr int BBYT = BN * SS * 2;
    constexpr int BUF = ABYT + 2 * BBYT;

    extern __shared__ char smem[];
    const uint32_t sb = smem_u32(smem);

    const int tid = threadIdx.x;
    const int wid = tid >> 5, lane = tid & 31;
    const int wm = wid % WARPS_M, wn = wid / WARPS_M;
    const int gr = lane >> 2, tq = lane & 3;

    const long m0 = (long)blockIdx.y * 128;
    const int  n0 = blockIdx.x * BN;
    const int  nc = K >> 5;

    float acc[MI][NI][4];
#pragma unroll
    for (int mi = 0; mi < MI; ++mi)
#pragma unroll
        for (int ni = 0; ni < NI; ++ni)
#pragma unroll
            for (int q = 0; q < 4; ++q) acc[mi][ni][q] = 0.0f;

    auto load_chunk = [&](int ch) {
        const int k0 = ch << 5;
        const half* ap; long ld, kk;
        if (k0 < ksplit) { ap = X_g; ld = ldx; kk = k0; }
        else             { ap = A_g; ld = lda; kk = k0 - ksplit; }
        const uint32_t base = sb + (ch & 1) * BUF;
#pragma unroll
        for (int it = 0; it < 2; ++it) {
            int e = tid + it * 256;
            int row = e >> 2, seg = e & 3;
            long go = (m0 + row) * ld + kk + seg * 8;
            cpa16(base + (uint32_t)(row * SS + seg * 8) * 2, ap + go);
        }
#pragma unroll
        for (int it = 0; it < BN / 64; ++it) {
            int e = tid + it * 256;
            int row = e >> 2, seg = e & 3;
            long go = (long)(n0 + row) * K + k0 + seg * 8;
            uint32_t d = base + ABYT + (uint32_t)(row * SS + seg * 8) * 2;
            cpa16(d, Bhi_g + go);
            cpa16(d + BBYT, Blo_g + go);
        }
    };

    load_chunk(0);
    cpa_commit();

    for (int ch = 0; ch < nc; ++ch) {
        if (ch > 0) __syncthreads();
        if (ch + 1 < nc) load_chunk(ch + 1);
        cpa_commit();
        cpa_wait1();
        __syncthreads();

        const half* As    = (const half*)(smem + (ch & 1) * BUF);
        const half* Bs_hi = (const half*)((const char*)As + ABYT);
        const half* Bs_lo = (const half*)((const char*)Bs_hi + BBYT);

#pragma unroll
        for (int k16 = 0; k16 < 2; ++k16) {
            const int kk = k16 * 16 + 2 * tq;
            uint32_t af[MI][4], bh[NI][2], bl[NI][2];
#pragma unroll
            for (int mi = 0; mi < MI; ++mi) {
                int r0 = wm * WM + mi * 16 + gr;
                af[mi][0] = *(const uint32_t*)(As + r0 * SS + kk);
                af[mi][1] = *(const uint32_t*)(As + (r0 + 8) * SS + kk);
                af[mi][2] = *(const uint32_t*)(As + r0 * SS + kk + 8);
                af[mi][3] = *(const uint32_t*)(As + (r0 + 8) * SS + kk + 8);
            }
#pragma unroll
            for (int ni = 0; ni < NI; ++ni) {
                int nn = wn * 32 + ni * 8 + gr;
                bh[ni][0] = *(const uint32_t*)(Bs_hi + nn * SS + kk);
                bh[ni][1] = *(const uint32_t*)(Bs_hi + nn * SS + kk + 8);
                bl[ni][0] = *(const uint32_t*)(Bs_lo + nn * SS + kk);
                bl[ni][1] = *(const uint32_t*)(Bs_lo + nn * SS + kk + 8);
            }
#pragma unroll
            for (int mi = 0; mi < MI; ++mi)
#pragma unroll
                for (int ni = 0; ni < NI; ++ni) {
                    mma16(acc[mi][ni], af[mi], bh[ni]);
                    mma16(acc[mi][ni], af[mi], bl[ni]);
                }
        }
    }

    // ---- epilogue ----
#pragma unroll
    for (int mi = 0; mi < MI; ++mi) {
#pragma unroll
        for (int ni = 0; ni < NI; ++ni) {
            const int col = n0 + wn * 32 + ni * 8 + 2 * tq;
            const long mA = m0 + wm * WM + mi * 16 + gr;      // rows gr / gr+8
            float2 bc = *(const float2*)(bias + col);
            float v0 = acc[mi][ni][0] + bc.x;
            float v1 = acc[mi][ni][1] + bc.y;
            float v2 = acc[mi][ni][2] + bc.x;
            float v3 = acc[mi][ni][3] + bc.y;

            if (EPI == 1 || EPI == 2) {
                if (EPI == 1) { v0 = tanhf(v0); v1 = tanhf(v1); v2 = tanhf(v2); v3 = tanhf(v3); }
                else {
                    *(float2*)(Cf + mA * ldc + col) = make_float2(v0, v1);
                    *(float2*)(Cf + (mA + 8) * ldc + col) = make_float2(v2, v3);
                }
                __half2 p0 = __floats2half2_rn(v0, v1);
                __half2 p1 = __floats2half2_rn(v2, v3);
                *(uint32_t*)(Ch + mA * ldc + col) = *(uint32_t*)&p0;
                *(uint32_t*)(Ch + (mA + 8) * ldc + col) = *(uint32_t*)&p1;
            } else if (EPI == 3) {
                long t1_ = (mA >> 12) + 1, b1_ = mA & 4095;
                long t2_ = ((mA + 8) >> 12) + 1, b2_ = (mA + 8) & 4095;
                *(float2*)(Cf + b1_ * (LL * AA) + t1_ * AA + col) = make_float2(v0, v1);
                *(float2*)(Cf + b2_ * (LL * AA) + t2_ * AA + col) = make_float2(v2, v3);
            } else {  // EPI == 4 : fused GRU gates, interleaved [r,z,nx,nh]
                float x0 = __shfl_xor_sync(0xFFFFFFFFu, v0, 1);
                float x1 = __shfl_xor_sync(0xFFFFFFFFu, v1, 1);
                float x2 = __shfl_xor_sync(0xFFFFFFFFu, v2, 1);
                float x3 = __shfl_xor_sync(0xFFFFFFFFu, v3, 1);
                const int j = ((n0 + wn * 32 + ni * 8) >> 2) + (tq >> 1);
                const long m = mA + ((tq & 1) ? 8 : 0);
                float rr, zz, nx, nh;
                if ((tq & 1) == 0) { rr = v0; zz = v1; nx = x0; nh = x1; }
                else               { rr = x2; zz = x3; nx = v2; nh = v3; }
                float r_ = sigf(rr), z_ = sigf(zz);
                float hp = hprev32[m * HH + j];
                float hv = (1.0f - z_) * tanhf(nx + r_ * nh) + z_ * hp;
                hnew32[m * HH + j] = hv;
                Ch[m * HH + j] = __float2half_rn(hv);
            }
        }
    }
}

// ============================================================
// Orchestration
// ============================================================
extern "C" void kernel_launch(void* const* d_in, const int* in_sizes, int n_in,
                              void* d_out, int out_size)
{
    const float* latent = (const float*)d_in[0];
    const float* target = (const float*)d_in[1];
    const float* Wd1 = (const float*)d_in[2];
    const float* bd1 = (const float*)d_in[3];
    const float* Wd2 = (const float*)d_in[4];
    const float* bd2 = (const float*)d_in[5];
    const float* Wd3 = (const float*)d_in[6];
    const float* bd3 = (const float*)d_in[7];
    const float* Wih = (const float*)d_in[8];
    const float* Whh = (const float*)d_in[9];
    const float* bih = (const float*)d_in[10];
    const float* bhh = (const float*)d_in[11];
    const float* Wm1 = (const float*)d_in[12];
    const float* bm1 = (const float*)d_in[13];
    const float* Wm2 = (const float*)d_in[14];
    const float* bm2 = (const float*)d_in[15];
    const float* Wm3 = (const float*)d_in[16];
    const float* bm3 = (const float*)d_in[17];
    float* out = (float*)d_out;

#define SYM(v, s) cudaGetSymbolAddress((void**)&v, s)
    half *Hd, *P1, *P2, *X, *H0, *t1, *t2, *L;
    half *Wcathi, *Wcatlo, *Wd1hi, *Wd1lo, *Wd2hi, *Wd2lo, *Wd3hi, *Wd3lo;
    half *Wm1hi, *Wm1lo, *Wm2hi, *Wm2lo, *Wm3hi, *Wm3lo;
    float *h32a, *h32b, *biascat;
    SYM(Hd, g_Hd); SYM(P1, g_P1); SYM(P2, g_P2); SYM(X, g_X);
    SYM(H0, g_H0); SYM(t1, g_t1); SYM(t2, g_t2); SYM(L, g_L);
    SYM(Wcathi, g_Wcathi); SYM(Wcatlo, g_Wcatlo);
    SYM(Wd1hi, g_Wd1hi); SYM(Wd1lo, g_Wd1lo);
    SYM(Wd2hi, g_Wd2hi); SYM(Wd2lo, g_Wd2lo);
    SYM(Wd3hi, g_Wd3hi); SYM(Wd3lo, g_Wd3lo);
    SYM(Wm1hi, g_Wm1hi); SYM(Wm1lo, g_Wm1lo);
    SYM(Wm2hi, g_Wm2hi); SYM(Wm2lo, g_Wm2lo);
    SYM(Wm3hi, g_Wm3hi); SYM(Wm3lo, g_Wm3lo);
    SYM(h32a, g_h32a); SYM(h32b, g_h32b); SYM(biascat, g_biascat);
#undef SYM

    const long M2 = (long)(LL - 1) * BB;  // 520192
    constexpr int SM128 = 2 * (128 * 40 * 2 + 2 * 128 * 40 * 2);   // 61440
    constexpr int SM64  = 2 * (128 * 40 * 2 + 2 * 64 * 40 * 2);    // 40960
    cudaFuncSetAttribute(mma_gemm<128, 1>, cudaFuncAttributeMaxDynamicSharedMemorySize, SM128);
    cudaFuncSetAttribute(mma_gemm<128, 2>, cudaFuncAttributeMaxDynamicSharedMemorySize, SM128);
    cudaFuncSetAttribute(mma_gemm<128, 4>, cudaFuncAttributeMaxDynamicSharedMemorySize, SM128);
    cudaFuncSetAttribute(mma_gemm<64, 1>,  cudaFuncAttributeMaxDynamicSharedMemorySize, SM64);
    cudaFuncSetAttribute(mma_gemm<64, 3>,  cudaFuncAttributeMaxDynamicSharedMemorySize, SM64);

    // ---- setup (ordered so the 4th launch is a REAL gates GEMM for ncu) ----
    build_X<<<(int)((M2 * AA) / 256), 256>>>(target, X);                         // 1
    build_wcat<<<(NGT * KGT + 255) / 256, 256>>>(Wih, Whh, Wcathi, Wcatlo);      // 2
    build_biascat<<<(NGT + 255) / 256, 256>>>(bih, bhh, biascat);                // 3
    // 4: dummy gates GEMM (profiling target). Inputs deterministic (H0/h32a
    // zero-init or overwritten-before-read); outputs (Hd slot0, h32b) are
    // rewritten by the real t=1 step before any consumer reads them.
    mma_gemm<128, 4><<<dim3(NGT / 128, BB / 128), 256, SM128>>>(
        H0, HH, X, AA, AA, Wcathi, Wcatlo, KGT, biascat,
        nullptr, HH, Hd, h32a, h32b);

    fill_bos_out<<<(BB * AA) / 256, 256>>>(out);
    tohalf<<<(BB * LAT + 255) / 256, 256>>>(latent, L, BB * LAT);
    split_h<<<(HH * LAT + 255) / 256, 256>>>(Wd1, Wd1hi, Wd1lo, HH * LAT);
    split_h<<<(HH * HH + 255) / 256, 256>>>(Wd2, Wd2hi, Wd2lo, HH * HH);
    split_h<<<(HH * HH + 255) / 256, 256>>>(Wd3, Wd3hi, Wd3lo, HH * HH);
    split_h<<<(HH * HH + 255) / 256, 256>>>(Wm1, Wm1hi, Wm1lo, HH * HH);
    split_h<<<(AA * HH + 255) / 256, 256>>>(Wm2, Wm2hi, Wm2lo, AA * HH);
    split_h<<<(AA * AA + 255) / 256, 256>>>(Wm3, Wm3hi, Wm3lo, AA * AA);

    // ---- h0 = Wd3(tanh(Wd2(tanh(Wd1(latent))))) ----
    mma_gemm<128, 1><<<dim3(HH / 128, BB / 128), 256, SM128>>>(
        L, LAT, nullptr, 0, 0, Wd1hi, Wd1lo, LAT, bd1,
        nullptr, HH, t1, nullptr, nullptr);
    mma_gemm<128, 1><<<dim3(HH / 128, BB / 128), 256, SM128>>>(
        t1, HH, nullptr, 0, 0, Wd2hi, Wd2lo, HH, bd2,
        nullptr, HH, t2, nullptr, nullptr);
    mma_gemm<128, 2><<<dim3(HH / 128, BB / 128), 256, SM128>>>(
        t2, HH, nullptr, 0, 0, Wd3hi, Wd3lo, HH, bd3,
        h32a, HH, H0, nullptr, nullptr);

    // ---- sequential GRU: one fused gemm+gate launch per step ----
    float* hp32 = h32a;
    float* hn32 = h32b;
    for (int t = 1; t < LL; ++t) {
        const half* hin = (t == 1) ? H0 : Hd + (size_t)(t - 2) * BB * HH;
        mma_gemm<128, 4><<<dim3(NGT / 128, BB / 128), 256, SM128>>>(
            hin, HH,
            X + (size_t)(t - 1) * BB * AA, AA, AA,
            Wcathi, Wcatlo, KGT, biascat,
            nullptr, HH,
            Hd + (size_t)(t - 1) * BB * HH,
            hp32, hn32);
        float* tmp = hp32; hp32 = hn32; hn32 = tmp;
    }

    // ---- per-step decoder over all 127 steps at once ----
    mma_gemm<128, 1><<<dim3(HH / 128, (int)(M2 / 128)), 256, SM128>>>(
        Hd, HH, nullptr, 0, 0, Wm1hi, Wm1lo, HH, bm1,
        nullptr, HH, P1, nullptr, nullptr);
    mma_gemm<64, 1><<<dim3(1, (int)(M2 / 128)), 256, SM64>>>(
        P1, HH, nullptr, 0, 0, Wm2hi, Wm2lo, HH, bm2,
        nullptr, AA, P2, nullptr, nullptr);
    mma_gemm<64, 3><<<dim3(1, (int)(M2 / 128)), 256, SM64>>>(
        P2, AA, nullptr, 0, 0, Wm3hi, Wm3lo, AA, bm3,
        out, 0, nullptr, nullptr, nullptr);
}

// round 8
// speedup vs baseline: 3.2105x; 1.3155x over previous
#include <cuda_runtime.h>
#include <cuda_fp16.h>
#include <math.h>
#include <stdint.h>

#define BB 4096
#define LAT 256
#define HH 512
#define AA 64
#define LL 128
#define NGT 2048         // gate gemm N: interleaved [r,z,nx,nh] per hidden j
#define KGT 576          // gate gemm K: [x(64) | h(512)]

// ---- scratch (static device globals; ~1.25 GB) ----
__device__ half  g_Hd[(size_t)(LL - 1) * BB * HH];     // h_t fp16, slots t=1..127
__device__ half  g_P1[(size_t)(LL - 1) * BB * HH];
__device__ half  g_P2[(size_t)(LL - 1) * BB * AA];
__device__ half  g_X[(size_t)(LL - 1) * BB * AA];
__device__ float g_h32a[(size_t)BB * HH];
__device__ float g_h32b[(size_t)BB * HH];
__device__ half  g_H0[(size_t)BB * HH];
__device__ half  g_t1[(size_t)BB * HH];
__device__ half  g_t2[(size_t)BB * HH];
__device__ half  g_L[(size_t)BB * LAT];
__device__ half  g_Wcathi[(size_t)NGT * KGT], g_Wcatlo[(size_t)NGT * KGT];
__device__ half  g_Wd1hi[HH * LAT], g_Wd1lo[HH * LAT];
__device__ half  g_Wd2hi[HH * HH],  g_Wd2lo[HH * HH];
__device__ half  g_Wd3hi[HH * HH],  g_Wd3lo[HH * HH];
__device__ half  g_Wm1hi[HH * HH],  g_Wm1lo[HH * HH];
__device__ half  g_Wm2hi[AA * HH],  g_Wm2lo[AA * HH];
__device__ half  g_Wm3hi[AA * AA],  g_Wm3lo[AA * AA];
__device__ float g_biascat[NGT];

// ============================================================
// helpers
// ============================================================
__device__ __forceinline__ uint32_t smem_u32(const void* p) {
    uint32_t a;
    asm("{ .reg .u64 t; cvta.to.shared.u64 t, %1; cvt.u32.u64 %0, t; }" : "=r"(a) : "l"(p));
    return a;
}
__device__ __forceinline__ void cpa16(uint32_t dst, const void* src) {
    asm volatile("cp.async.cg.shared.global [%0], [%1], 16;" :: "r"(dst), "l"(src));
}
__device__ __forceinline__ void cpa_commit() {
    asm volatile("cp.async.commit_group;" ::: "memory");
}
__device__ __forceinline__ void cpa_wait1() {
    asm volatile("cp.async.wait_group 1;" ::: "memory");
}
__device__ __forceinline__ void hsplit(float v, half& hi, half& lo) {
    hi = __float2half_rn(v);
    lo = __float2half_rn(v - __half2float(hi));
}
__device__ __forceinline__ float sigf(float x) { return 1.0f / (1.0f + expf(-x)); }

__device__ __forceinline__ void mma16(float d[4], const uint32_t a[4], const uint32_t b[2]) {
    asm volatile(
        "mma.sync.aligned.m16n8k16.row.col.f32.f16.f16.f32 "
        "{%0,%1,%2,%3},{%4,%5,%6,%7},{%8,%9},{%0,%1,%2,%3};"
        : "+f"(d[0]), "+f"(d[1]), "+f"(d[2]), "+f"(d[3])
        : "r"(a[0]), "r"(a[1]), "r"(a[2]), "r"(a[3]), "r"(b[0]), "r"(b[1]));
}
__device__ __forceinline__ void ldsm_x4(uint32_t r[4], uint32_t addr) {
    asm volatile("ldmatrix.sync.aligned.m8n8.x4.shared.b16 {%0,%1,%2,%3}, [%4];"
                 : "=r"(r[0]), "=r"(r[1]), "=r"(r[2]), "=r"(r[3]) : "r"(addr));
}

// ============================================================
// Setup kernels
// ============================================================
__global__ void fill_bos_out(float* __restrict__ out) {
    int idx = blockIdx.x * blockDim.x + threadIdx.x;   // [0, BB*AA)
    int b = idx >> 6, a = idx & 63;
    out[(size_t)b * (LL * AA) + a] = (a == 0) ? 16.0f : -16.0f;
}
// X[(t-1)*BB + b][a] : t=1 -> bos ; t>=2 -> target[b][t-1][a]
__global__ void build_X(const float* __restrict__ target, half* __restrict__ X) {
    size_t idx = (size_t)blockIdx.x * blockDim.x + threadIdx.x;
    int a = (int)(idx & 63);
    size_t row = idx >> 6;
    int trow = (int)(row >> 12);
    int b = (int)(row & 4095);
    float v;
    if (trow == 0) v = (a == 0) ? 16.0f : -16.0f;
    else           v = target[((size_t)b << 13) + (size_t)trow * AA + a];
    X[idx] = __float2half_rn(v);
}
__global__ void tohalf(const float* __restrict__ src, half* __restrict__ dst, int n) {
    int i = blockIdx.x * blockDim.x + threadIdx.x;
    if (i < n) dst[i] = __float2half_rn(src[i]);
}
__global__ void split_h(const float* __restrict__ src, half* __restrict__ hi,
                        half* __restrict__ lo, int n) {
    int i = blockIdx.x * blockDim.x + threadIdx.x;
    if (i < n) { half h, l; hsplit(src[i], h, l); hi[i] = h; lo[i] = l; }
}
// interleaved gate rows: row 4j+g, g in {0:r, 1:z, 2:nx, 3:nh}
__global__ void build_wcat(const float* __restrict__ Wih, const float* __restrict__ Whh,
                           half* __restrict__ hi, half* __restrict__ lo) {
    int i = blockIdx.x * blockDim.x + threadIdx.x;     // [0, NGT*KGT)
    if (i >= NGT * KGT) return;
    int k = i % KGT, row = i / KGT;
    int j = row >> 2, gg = row & 3;
    float v;
    if (gg == 0)      v = (k < AA) ? Wih[j * AA + k]          : Whh[(size_t)j * HH + k - AA];
    else if (gg == 1) v = (k < AA) ? Wih[(512 + j) * AA + k]  : Whh[(size_t)(512 + j) * HH + k - AA];
    else if (gg == 2) v = (k < AA) ? Wih[(1024 + j) * AA + k] : 0.0f;
    else              v = (k < AA) ? 0.0f                      : Whh[(size_t)(1024 + j) * HH + k - AA];
    half h, l; hsplit(v, h, l);
    hi[i] = h; lo[i] = l;
}
__global__ void build_biascat(const float* __restrict__ bih, const float* __restrict__ bhh,
                              float* __restrict__ bc) {
    int i = blockIdx.x * blockDim.x + threadIdx.x;
    if (i >= NGT) return;
    int j = i >> 2, gg = i & 3;
    float v;
    if (gg == 0)      v = bih[j] + bhh[j];
    else if (gg == 1) v = bih[512 + j] + bhh[512 + j];
    else if (gg == 2) v = bih[1024 + j];
    else              v = bhh[1024 + j];
    bc[i] = v;
}

// ============================================================
// fp16 2-term split GEMM: C = epi(A[M,K] @ W[N,K]^T + bias)
// A single fp16; B hi/lo fp16. acc += A*Bhi + A*Blo (fp32 acc).
// BM=128, BN in {128,64}, BK=32, 256 threads, 2 CTAs/SM,
// cp.async double buffer, ldmatrix fragment loads.
// EPI: 1 = tanh -> fp16; 2 = f32 + fp16; 3 = scatter f32 out[b][t][n];
//      4 = fused GRU gate epilogue (interleaved [r,z,nx,nh]).
// ============================================================
template <int BN, int EPI>
__global__ void __launch_bounds__(256, 2)
mma_gemm(const half* __restrict__ A_g, long lda,
         const half* __restrict__ X_g, long ldx, int ksplit,
         const half* __restrict__ Bhi_g, const half* __restrict__ Blo_g, int K,
         const float* __restrict__ bias,
         float* __restrict__ Cf, long ldc,
         half* __restrict__ Ch,
         const float* __restrict__ hprev32, float* __restrict__ hnew32)
{
    constexpr int SS = 40;                      // smem row stride (halfs)
    constexpr int WARPS_M = (BN == 128) ? 2 : 4;
    constexpr int WM = 128 / WARPS_M;           // 64 or 32
    constexpr int MI = WM / 16;                 // 4 or 2
    constexpr int NI = 4;                       // warp N tile = 32
    constexpr int ABYT = 128 * SS * 2;          // 10240 B
    constexpr int BBYT = BN * SS * 2;
    constexpr int BUF = ABYT + 2 * BBYT;

    extern __shared__ char smem[];
    const uint32_t sb = smem_u32(smem);

    const int tid = threadIdx.x;
    const int wid = tid >> 5, lane = tid & 31;
    const int wm = wid % WARPS_M, wn = wid / WARPS_M;
    const int gr = lane >> 2, tq = lane & 3;

    // ldmatrix per-lane row/col offsets
    const int aro = (lane & 7) + ((lane >> 3) & 1) * 8;   // m offset within fragment
    const int aco = (lane >> 4) * 8;                      // k offset
    const int bro = ((lane >> 4) & 1) * 8 + (lane & 7);   // n offset within ni-pair
    const int bko = ((lane >> 3) & 1) * 8;                // k offset

    const long m0 = (long)blockIdx.y * 128;
    const int  n0 = blockIdx.x * BN;
    const int  nc = K >> 5;

    float acc[MI][NI][4];
#pragma unroll
    for (int mi = 0; mi < MI; ++mi)
#pragma unroll
        for (int ni = 0; ni < NI; ++ni)
#pragma unroll
            for (int q = 0; q < 4; ++q) acc[mi][ni][q] = 0.0f;

    auto load_chunk = [&](int ch) {
        const int k0 = ch << 5;
        const half* ap; long ld, kk;
        if (k0 < ksplit) { ap = X_g; ld = ldx; kk = k0; }
        else             { ap = A_g; ld = lda; kk = k0 - ksplit; }
        const uint32_t base = sb + (ch & 1) * BUF;
#pragma unroll
        for (int it = 0; it < 2; ++it) {
            int e = tid + it * 256;
            int row = e >> 2, seg = e & 3;
            long go = (m0 + row) * ld + kk + seg * 8;
            cpa16(base + (uint32_t)(row * SS + seg * 8) * 2, ap + go);
        }
#pragma unroll
        for (int it = 0; it < BN / 64; ++it) {
            int e = tid + it * 256;
            int row = e >> 2, seg = e & 3;
            long go = (long)(n0 + row) * K + k0 + seg * 8;
            uint32_t d = base + ABYT + (uint32_t)(row * SS + seg * 8) * 2;
            cpa16(d, Bhi_g + go);
            cpa16(d + BBYT, Blo_g + go);
        }
    };

    load_chunk(0);
    cpa_commit();

    for (int ch = 0; ch < nc; ++ch) {
        if (ch > 0) __syncthreads();
        if (ch + 1 < nc) load_chunk(ch + 1);
        cpa_commit();
        cpa_wait1();
        __syncthreads();

        const uint32_t aBase = sb + (ch & 1) * BUF;
        const uint32_t bBase = aBase + ABYT;

#pragma unroll
        for (int k16 = 0; k16 < 2; ++k16) {
            const int kk = k16 * 16;
            uint32_t af[MI][4], bh[NI][2], bl[NI][2];
#pragma unroll
            for (int mi = 0; mi < MI; ++mi) {
                uint32_t a = aBase + (uint32_t)((wm * WM + mi * 16 + aro) * SS + kk + aco) * 2;
                ldsm_x4(af[mi], a);
            }
#pragma unroll
            for (int n2 = 0; n2 < NI / 2; ++n2) {
                uint32_t a = bBase + (uint32_t)((wn * 32 + n2 * 16 + bro) * SS + kk + bko) * 2;
                ldsm_x4(&bh[2 * n2][0], a);
                ldsm_x4(&bl[2 * n2][0], a + BBYT);
            }
#pragma unroll
            for (int mi = 0; mi < MI; ++mi)
#pragma unroll
                for (int ni = 0; ni < NI; ++ni) {
                    mma16(acc[mi][ni], af[mi], bh[ni]);
                    mma16(acc[mi][ni], af[mi], bl[ni]);
                }
        }
    }

    // ---- epilogue ----
#pragma unroll
    for (int mi = 0; mi < MI; ++mi) {
#pragma unroll
        for (int ni = 0; ni < NI; ++ni) {
            const int col = n0 + wn * 32 + ni * 8 + 2 * tq;
            const long mA = m0 + wm * WM + mi * 16 + gr;      // rows gr / gr+8
            float2 bc = *(const float2*)(bias + col);
            float v0 = acc[mi][ni][0] + bc.x;
            float v1 = acc[mi][ni][1] + bc.y;
            float v2 = acc[mi][ni][2] + bc.x;
            float v3 = acc[mi][ni][3] + bc.y;

            if (EPI == 1 || EPI == 2) {
                if (EPI == 1) { v0 = tanhf(v0); v1 = tanhf(v1); v2 = tanhf(v2); v3 = tanhf(v3); }
                else {
                    *(float2*)(Cf + mA * ldc + col) = make_float2(v0, v1);
                    *(float2*)(Cf + (mA + 8) * ldc + col) = make_float2(v2, v3);
                }
                __half2 p0 = __floats2half2_rn(v0, v1);
                __half2 p1 = __floats2half2_rn(v2, v3);
                *(uint32_t*)(Ch + mA * ldc + col) = *(uint32_t*)&p0;
                *(uint32_t*)(Ch + (mA + 8) * ldc + col) = *(uint32_t*)&p1;
            } else if (EPI == 3) {
                long t1_ = (mA >> 12) + 1, b1_ = mA & 4095;
                long t2_ = ((mA + 8) >> 12) + 1, b2_ = (mA + 8) & 4095;
                *(float2*)(Cf + b1_ * (LL * AA) + t1_ * AA + col) = make_float2(v0, v1);
                *(float2*)(Cf + b2_ * (LL * AA) + t2_ * AA + col) = make_float2(v2, v3);
            } else {  // EPI == 4 : fused GRU gates, interleaved [r,z,nx,nh]
                float x0 = __shfl_xor_sync(0xFFFFFFFFu, v0, 1);
                float x1 = __shfl_xor_sync(0xFFFFFFFFu, v1, 1);
                float x2 = __shfl_xor_sync(0xFFFFFFFFu, v2, 1);
                float x3 = __shfl_xor_sync(0xFFFFFFFFu, v3, 1);
                const int j = ((n0 + wn * 32 + ni * 8) >> 2) + (tq >> 1);
                const long m = mA + ((tq & 1) ? 8 : 0);
                float rr, zz, nx, nh;
                if ((tq & 1) == 0) { rr = v0; zz = v1; nx = x0; nh = x1; }
                else               { rr = x2; zz = x3; nx = v2; nh = v3; }
                float r_ = sigf(rr), z_ = sigf(zz);
                float hp = hprev32[m * HH + j];
                float hv = (1.0f - z_) * tanhf(nx + r_ * nh) + z_ * hp;
                hnew32[m * HH + j] = hv;
                Ch[m * HH + j] = __float2half_rn(hv);
            }
        }
    }
}

// ============================================================
// Orchestration
// ============================================================
extern "C" void kernel_launch(void* const* d_in, const int* in_sizes, int n_in,
                              void* d_out, int out_size)
{
    const float* latent = (const float*)d_in[0];
    const float* target = (const float*)d_in[1];
    const float* Wd1 = (const float*)d_in[2];
    const float* bd1 = (const float*)d_in[3];
    const float* Wd2 = (const float*)d_in[4];
    const float* bd2 = (const float*)d_in[5];
    const float* Wd3 = (const float*)d_in[6];
    const float* bd3 = (const float*)d_in[7];
    const float* Wih = (const float*)d_in[8];
    const float* Whh = (const float*)d_in[9];
    const float* bih = (const float*)d_in[10];
    const float* bhh = (const float*)d_in[11];
    const float* Wm1 = (const float*)d_in[12];
    const float* bm1 = (const float*)d_in[13];
    const float* Wm2 = (const float*)d_in[14];
    const float* bm2 = (const float*)d_in[15];
    const float* Wm3 = (const float*)d_in[16];
    const float* bm3 = (const float*)d_in[17];
    float* out = (float*)d_out;

#define SYM(v, s) cudaGetSymbolAddress((void**)&v, s)
    half *Hd, *P1, *P2, *X, *H0, *t1, *t2, *L;
    half *Wcathi, *Wcatlo, *Wd1hi, *Wd1lo, *Wd2hi, *Wd2lo, *Wd3hi, *Wd3lo;
    half *Wm1hi, *Wm1lo, *Wm2hi, *Wm2lo, *Wm3hi, *Wm3lo;
    float *h32a, *h32b, *biascat;
    SYM(Hd, g_Hd); SYM(P1, g_P1); SYM(P2, g_P2); SYM(X, g_X);
    SYM(H0, g_H0); SYM(t1, g_t1); SYM(t2, g_t2); SYM(L, g_L);
    SYM(Wcathi, g_Wcathi); SYM(Wcatlo, g_Wcatlo);
    SYM(Wd1hi, g_Wd1hi); SYM(Wd1lo, g_Wd1lo);
    SYM(Wd2hi, g_Wd2hi); SYM(Wd2lo, g_Wd2lo);
    SYM(Wd3hi, g_Wd3hi); SYM(Wd3lo, g_Wd3lo);
    SYM(Wm1hi, g_Wm1hi); SYM(Wm1lo, g_Wm1lo);
    SYM(Wm2hi, g_Wm2hi); SYM(Wm2lo, g_Wm2lo);
    SYM(Wm3hi, g_Wm3hi); SYM(Wm3lo, g_Wm3lo);
    SYM(h32a, g_h32a); SYM(h32b, g_h32b); SYM(biascat, g_biascat);
#undef SYM

    const long M2 = (long)(LL - 1) * BB;  // 520192
    constexpr int SM128 = 2 * (128 * 40 * 2 + 2 * 128 * 40 * 2);   // 61440
    constexpr int SM64  = 2 * (128 * 40 * 2 + 2 * 64 * 40 * 2);    // 40960
    cudaFuncSetAttribute(mma_gemm<128, 1>, cudaFuncAttributeMaxDynamicSharedMemorySize, SM128);
    cudaFuncSetAttribute(mma_gemm<128, 2>, cudaFuncAttributeMaxDynamicSharedMemorySize, SM128);
    cudaFuncSetAttribute(mma_gemm<128, 4>, cudaFuncAttributeMaxDynamicSharedMemorySize, SM128);
    cudaFuncSetAttribute(mma_gemm<64, 1>,  cudaFuncAttributeMaxDynamicSharedMemorySize, SM64);
    cudaFuncSetAttribute(mma_gemm<64, 3>,  cudaFuncAttributeMaxDynamicSharedMemorySize, SM64);

    // ---- setup (ordered so the 4th launch is a REAL gates GEMM for ncu) ----
    build_X<<<(int)((M2 * AA) / 256), 256>>>(target, X);                         // 1
    build_wcat<<<(NGT * KGT + 255) / 256, 256>>>(Wih, Whh, Wcathi, Wcatlo);      // 2
    build_biascat<<<(NGT + 255) / 256, 256>>>(bih, bhh, biascat);                // 3
    // 4: dummy gates GEMM (profiling target). Inputs deterministic; outputs
    // (Hd slot0, h32b) are rewritten by the real t=1 step before consumption.
    mma_gemm<128, 4><<<dim3(NGT / 128, BB / 128), 256, SM128>>>(
        H0, HH, X, AA, AA, Wcathi, Wcatlo, KGT, biascat,
        nullptr, HH, Hd, h32a, h32b);

    fill_bos_out<<<(BB * AA) / 256, 256>>>(out);
    tohalf<<<(BB * LAT + 255) / 256, 256>>>(latent, L, BB * LAT);
    split_h<<<(HH * LAT + 255) / 256, 256>>>(Wd1, Wd1hi, Wd1lo, HH * LAT);
    split_h<<<(HH * HH + 255) / 256, 256>>>(Wd2, Wd2hi, Wd2lo, HH * HH);
    split_h<<<(HH * HH + 255) / 256, 256>>>(Wd3, Wd3hi, Wd3lo, HH * HH);
    split_h<<<(HH * HH + 255) / 256, 256>>>(Wm1, Wm1hi, Wm1lo, HH * HH);
    split_h<<<(AA * HH + 255) / 256, 256>>>(Wm2, Wm2hi, Wm2lo, AA * HH);
    split_h<<<(AA * AA + 255) / 256, 256>>>(Wm3, Wm3hi, Wm3lo, AA * AA);

    // ---- h0 = Wd3(tanh(Wd2(tanh(Wd1(latent))))) ----
    mma_gemm<128, 1><<<dim3(HH / 128, BB / 128), 256, SM128>>>(
        L, LAT, nullptr, 0, 0, Wd1hi, Wd1lo, LAT, bd1,
        nullptr, HH, t1, nullptr, nullptr);
    mma_gemm<128, 1><<<dim3(HH / 128, BB / 128), 256, SM128>>>(
        t1, HH, nullptr, 0, 0, Wd2hi, Wd2lo, HH, bd2,
        nullptr, HH, t2, nullptr, nullptr);
    mma_gemm<128, 2><<<dim3(HH / 128, BB / 128), 256, SM128>>>(
        t2, HH, nullptr, 0, 0, Wd3hi, Wd3lo, HH, bd3,
        h32a, HH, H0, nullptr, nullptr);

    // ---- sequential GRU: one fused gemm+gate launch per step ----
    float* hp32 = h32a;
    float* hn32 = h32b;
    for (int t = 1; t < LL; ++t) {
        const half* hin = (t == 1) ? H0 : Hd + (size_t)(t - 2) * BB * HH;
        mma_gemm<128, 4><<<dim3(NGT / 128, BB / 128), 256, SM128>>>(
            hin, HH,
            X + (size_t)(t - 1) * BB * AA, AA, AA,
            Wcathi, Wcatlo, KGT, biascat,
            nullptr, HH,
            Hd + (size_t)(t - 1) * BB * HH,
            hp32, hn32);
        float* tmp = hp32; hp32 = hn32; hn32 = tmp;
    }

    // ---- per-step decoder over all 127 steps at once ----
    mma_gemm<128, 1><<<dim3(HH / 128, (int)(M2 / 128)), 256, SM128>>>(
        Hd, HH, nullptr, 0, 0, Wm1hi, Wm1lo, HH, bm1,
        nullptr, HH, P1, nullptr, nullptr);
    mma_gemm<64, 1><<<dim3(1, (int)(M2 / 128)), 256, SM64>>>(
        P1, HH, nullptr, 0, 0, Wm2hi, Wm2lo, HH, bm2,
        nullptr, AA, P2, nullptr, nullptr);
    mma_gemm<64, 3><<<dim3(1, (int)(M2 / 128)), 256, SM64>>>(
        P2, AA, nullptr, 0, 0, Wm3hi, Wm3lo, AA, bm3,
        out, 0, nullptr, nullptr, nullptr);
}

// round 9
// speedup vs baseline: 4.9911x; 1.5546x over previous
#include <cuda_runtime.h>
#include <cuda_fp16.h>
#include <math.h>
#include <stdint.h>

#define BB 4096
#define LAT 256
#define HH 512
#define AA 64
#define LL 128
#define NGT 2048         // gate gemm N: interleaved [r,z,nx,nh] per hidden j
#define KGT 576          // gate gemm K: [x(64) | h(512)]

// ---- scratch (static device globals; ~0.75 GB) ----
__device__ half  g_Hd[(size_t)(LL - 1) * BB * HH];     // h_t fp16, slots t=1..127
__device__ half  g_P1[(size_t)(LL - 1) * BB * HH];
__device__ half  g_P2[(size_t)(LL - 1) * BB * AA];
__device__ half  g_X[(size_t)(LL - 1) * BB * AA];
__device__ float g_h32a[(size_t)BB * HH];
__device__ float g_h32b[(size_t)BB * HH];
__device__ half  g_H0[(size_t)BB * HH];
__device__ half  g_t1[(size_t)BB * HH];
__device__ half  g_t2[(size_t)BB * HH];
__device__ half  g_L[(size_t)BB * LAT];
__device__ half  g_Wcat[(size_t)NGT * KGT];
__device__ half  g_Wd1[HH * LAT];
__device__ half  g_Wd2[HH * HH];
__device__ half  g_Wd3[HH * HH];
__device__ half  g_Wm1[HH * HH];
__device__ half  g_Wm2[AA * HH];
__device__ half  g_Wm3[AA * AA];
__device__ float g_biascat[NGT];

// ============================================================
// helpers
// ============================================================
__device__ __forceinline__ uint32_t smem_u32(const void* p) {
    uint32_t a;
    asm("{ .reg .u64 t; cvta.to.shared.u64 t, %1; cvt.u32.u64 %0, t; }" : "=r"(a) : "l"(p));
    return a;
}
__device__ __forceinline__ void cpa16(uint32_t dst, const void* src) {
    asm volatile("cp.async.cg.shared.global [%0], [%1], 16;" :: "r"(dst), "l"(src));
}
__device__ __forceinline__ void cpa_commit() {
    asm volatile("cp.async.commit_group;" ::: "memory");
}
__device__ __forceinline__ void cpa_wait1() {
    asm volatile("cp.async.wait_group 1;" ::: "memory");
}
__device__ __forceinline__ float sigf(float x) { return 1.0f / (1.0f + expf(-x)); }

__device__ __forceinline__ void mma16(float d[4], const uint32_t a[4], const uint32_t b[2]) {
    asm volatile(
        "mma.sync.aligned.m16n8k16.row.col.f32.f16.f16.f32 "
        "{%0,%1,%2,%3},{%4,%5,%6,%7},{%8,%9},{%0,%1,%2,%3};"
        : "+f"(d[0]), "+f"(d[1]), "+f"(d[2]), "+f"(d[3])
        : "r"(a[0]), "r"(a[1]), "r"(a[2]), "r"(a[3]), "r"(b[0]), "r"(b[1]));
}
__device__ __forceinline__ void ldsm_x4(uint32_t r[4], uint32_t addr) {
    asm volatile("ldmatrix.sync.aligned.m8n8.x4.shared.b16 {%0,%1,%2,%3}, [%4];"
                 : "=r"(r[0]), "=r"(r[1]), "=r"(r[2]), "=r"(r[3]) : "r"(addr));
}

// ============================================================
// Setup kernels
// ============================================================
__global__ void fill_bos_out(float* __restrict__ out) {
    int idx = blockIdx.x * blockDim.x + threadIdx.x;   // [0, BB*AA)
    int b = idx >> 6, a = idx & 63;
    out[(size_t)b * (LL * AA) + a] = (a == 0) ? 16.0f : -16.0f;
}
// X[(t-1)*BB + b][a] : t=1 -> bos ; t>=2 -> target[b][t-1][a]
__global__ void build_X(const float* __restrict__ target, half* __restrict__ X) {
    size_t idx = (size_t)blockIdx.x * blockDim.x + threadIdx.x;
    int a = (int)(idx & 63);
    size_t row = idx >> 6;
    int trow = (int)(row >> 12);
    int b = (int)(row & 4095);
    float v;
    if (trow == 0) v = (a == 0) ? 16.0f : -16.0f;
    else           v = target[((size_t)b << 13) + (size_t)trow * AA + a];
    X[idx] = __float2half_rn(v);
}
__global__ void tohalf(const float* __restrict__ src, half* __restrict__ dst, int n) {
    int i = blockIdx.x * blockDim.x + threadIdx.x;
    if (i < n) dst[i] = __float2half_rn(src[i]);
}
// interleaved gate rows: row 4j+g, g in {0:r, 1:z, 2:nx, 3:nh}
__global__ void build_wcat(const float* __restrict__ Wih, const float* __restrict__ Whh,
                           half* __restrict__ w) {
    int i = blockIdx.x * blockDim.x + threadIdx.x;     // [0, NGT*KGT)
    if (i >= NGT * KGT) return;
    int k = i % KGT, row = i / KGT;
    int j = row >> 2, gg = row & 3;
    float v;
    if (gg == 0)      v = (k < AA) ? Wih[j * AA + k]          : Whh[(size_t)j * HH + k - AA];
    else if (gg == 1) v = (k < AA) ? Wih[(512 + j) * AA + k]  : Whh[(size_t)(512 + j) * HH + k - AA];
    else if (gg == 2) v = (k < AA) ? Wih[(1024 + j) * AA + k] : 0.0f;
    else              v = (k < AA) ? 0.0f                      : Whh[(size_t)(1024 + j) * HH + k - AA];
    w[i] = __float2half_rn(v);
}
__global__ void build_biascat(const float* __restrict__ bih, const float* __restrict__ bhh,
                              float* __restrict__ bc) {
    int i = blockIdx.x * blockDim.x + threadIdx.x;
    if (i >= NGT) return;
    int j = i >> 2, gg = i & 3;
    float v;
    if (gg == 0)      v = bih[j] + bhh[j];
    else if (gg == 1) v = bih[512 + j] + bhh[512 + j];
    else if (gg == 2) v = bih[1024 + j];
    else              v = bhh[1024 + j];
    bc[i] = v;
}

// ============================================================
// fp16 GEMM: C = epi(A[M,K] @ W[N,K]^T + bias), fp32 accum.
// BM=128, BN in {128,64}, BK=64, 256 threads, 2 CTAs/SM,
// cp.async double buffer, ldmatrix fragment loads.
// A source split at ksplit (k<ksplit -> X pointer). K%64==0.
// EPI: 1 = tanh -> fp16; 2 = f32 + fp16; 3 = scatter f32 out[b][t][n];
//      4 = fused GRU gate epilogue (interleaved [r,z,nx,nh]).
// ============================================================
template <int BN, int EPI>
__global__ void __launch_bounds__(256, 2)
mma_gemm(const half* __restrict__ A_g, long lda,
         const half* __restrict__ X_g, long ldx, int ksplit,
         const half* __restrict__ B_g, int K,
         const float* __restrict__ bias,
         float* __restrict__ Cf, long ldc,
         half* __restrict__ Ch,
         const float* __restrict__ hprev32, float* __restrict__ hnew32)
{
    constexpr int SS = 72;                      // smem row stride (halfs): 64 + 8 pad
    constexpr int WARPS_M = (BN == 128) ? 2 : 4;
    constexpr int WM = 128 / WARPS_M;           // 64 or 32
    constexpr int MI = WM / 16;                 // 4 or 2
    constexpr int NI = 4;                       // warp N tile = 32
    constexpr int ABYT = 128 * SS * 2;          // 18432 B
    constexpr int BBYT = BN * SS * 2;
    constexpr int BUF = ABYT + BBYT;

    extern __shared__ char smem[];
    const uint32_t sb = smem_u32(smem);

    const int tid = threadIdx.x;
    const int wid = tid >> 5, lane = tid & 31;
    const int wm = wid % WARPS_M, wn = wid / WARPS_M;
    const int gr = lane >> 2, tq = lane & 3;

    // ldmatrix per-lane row/col offsets
    const int aro = (lane & 7) + ((lane >> 3) & 1) * 8;   // m offset within fragment
    const int aco = (lane >> 4) * 8;                      // k offset
    const int bro = ((lane >> 4) & 1) * 8 + (lane & 7);   // n offset within ni-pair
    const int bko = ((lane >> 3) & 1) * 8;                // k offset

    const long m0 = (long)blockIdx.y * 128;
    const int  n0 = blockIdx.x * BN;
    const int  nc = K >> 6;

    float acc[MI][NI][4];
#pragma unroll
    for (int mi = 0; mi < MI; ++mi)
#pragma unroll
        for (int ni = 0; ni < NI; ++ni)
#pragma unroll
            for (int q = 0; q < 4; ++q) acc[mi][ni][q] = 0.0f;

    auto load_chunk = [&](int ch) {
        const int k0 = ch << 6;
        const half* ap; long ld, kk;
        if (k0 < ksplit) { ap = X_g; ld = ldx; kk = k0; }
        else             { ap = A_g; ld = lda; kk = k0 - ksplit; }
        const uint32_t base = sb + (ch & 1) * BUF;
#pragma unroll
        for (int it = 0; it < 4; ++it) {
            int e = tid + it * 256;
            int row = e >> 3, seg = e & 7;
            long go = (m0 + row) * ld + kk + seg * 8;
            cpa16(base + (uint32_t)(row * SS + seg * 8) * 2, ap + go);
        }
#pragma unroll
        for (int it = 0; it < BN / 32; ++it) {
            int e = tid + it * 256;
            int row = e >> 3, seg = e & 7;
            long go = (long)(n0 + row) * K + k0 + seg * 8;
            cpa16(base + ABYT + (uint32_t)(row * SS + seg * 8) * 2, B_g + go);
        }
    };

    load_chunk(0);
    cpa_commit();

    for (int ch = 0; ch < nc; ++ch) {
        if (ch > 0) __syncthreads();
        if (ch + 1 < nc) load_chunk(ch + 1);
        cpa_commit();
        cpa_wait1();
        __syncthreads();

        const uint32_t aBase = sb + (ch & 1) * BUF;
        const uint32_t bBase = aBase + ABYT;

#pragma unroll
        for (int k16 = 0; k16 < 4; ++k16) {
            const int kk = k16 * 16;
            uint32_t af[MI][4], bf[NI][2];
#pragma unroll
            for (int mi = 0; mi < MI; ++mi) {
                uint32_t a = aBase + (uint32_t)((wm * WM + mi * 16 + aro) * SS + kk + aco) * 2;
                ldsm_x4(af[mi], a);
            }
#pragma unroll
            for (int n2 = 0; n2 < NI / 2; ++n2) {
                uint32_t a = bBase + (uint32_t)((wn * 32 + n2 * 16 + bro) * SS + kk + bko) * 2;
                ldsm_x4(&bf[2 * n2][0], a);
            }
#pragma unroll
            for (int mi = 0; mi < MI; ++mi)
#pragma unroll
                for (int ni = 0; ni < NI; ++ni)
                    mma16(acc[mi][ni], af[mi], bf[ni]);
        }
    }

    // ---- epilogue ----
#pragma unroll
    for (int mi = 0; mi < MI; ++mi) {
#pragma unroll
        for (int ni = 0; ni < NI; ++ni) {
            const int col = n0 + wn * 32 + ni * 8 + 2 * tq;
            const long mA = m0 + wm * WM + mi * 16 + gr;      // rows gr / gr+8
            float2 bc = *(const float2*)(bias + col);
            float v0 = acc[mi][ni][0] + bc.x;
            float v1 = acc[mi][ni][1] + bc.y;
            float v2 = acc[mi][ni][2] + bc.x;
            float v3 = acc[mi][ni][3] + bc.y;

            if (EPI == 1 || EPI == 2) {
                if (EPI == 1) { v0 = tanhf(v0); v1 = tanhf(v1); v2 = tanhf(v2); v3 = tanhf(v3); }
                else {
                    *(float2*)(Cf + mA * ldc + col) = make_float2(v0, v1);
                    *(float2*)(Cf + (mA + 8) * ldc + col) = make_float2(v2, v3);
                }
                __half2 p0 = __floats2half2_rn(v0, v1);
                __half2 p1 = __floats2half2_rn(v2, v3);
                *(uint32_t*)(Ch + mA * ldc + col) = *(uint32_t*)&p0;
                *(uint32_t*)(Ch + (mA + 8) * ldc + col) = *(uint32_t*)&p1;
            } else if (EPI == 3) {
                long t1_ = (mA >> 12) + 1, b1_ = mA & 4095;
                long t2_ = ((mA + 8) >> 12) + 1, b2_ = (mA + 8) & 4095;
                *(float2*)(Cf + b1_ * (LL * AA) + t1_ * AA + col) = make_float2(v0, v1);
                *(float2*)(Cf + b2_ * (LL * AA) + t2_ * AA + col) = make_float2(v2, v3);
            } else {  // EPI == 4 : fused GRU gates, interleaved [r,z,nx,nh]
                float x0 = __shfl_xor_sync(0xFFFFFFFFu, v0, 1);
                float x1 = __shfl_xor_sync(0xFFFFFFFFu, v1, 1);
                float x2 = __shfl_xor_sync(0xFFFFFFFFu, v2, 1);
                float x3 = __shfl_xor_sync(0xFFFFFFFFu, v3, 1);
                const int j = ((n0 + wn * 32 + ni * 8) >> 2) + (tq >> 1);
                const long m = mA + ((tq & 1) ? 8 : 0);
                float rr, zz, nx, nh;
                if ((tq & 1) == 0) { rr = v0; zz = v1; nx = x0; nh = x1; }
                else               { rr = x2; zz = x3; nx = v2; nh = v3; }
                float r_ = sigf(rr), z_ = sigf(zz);
                float hp = hprev32[m * HH + j];
                float hv = (1.0f - z_) * tanhf(nx + r_ * nh) + z_ * hp;
                hnew32[m * HH + j] = hv;
                Ch[m * HH + j] = __float2half_rn(hv);
            }
        }
    }
}

// ============================================================
// Orchestration
// ============================================================
extern "C" void kernel_launch(void* const* d_in, const int* in_sizes, int n_in,
                              void* d_out, int out_size)
{
    const float* latent = (const float*)d_in[0];
    const float* target = (const float*)d_in[1];
    const float* Wd1 = (const float*)d_in[2];
    const float* bd1 = (const float*)d_in[3];
    const float* Wd2 = (const float*)d_in[4];
    const float* bd2 = (const float*)d_in[5];
    const float* Wd3 = (const float*)d_in[6];
    const float* bd3 = (const float*)d_in[7];
    const float* Wih = (const float*)d_in[8];
    const float* Whh = (const float*)d_in[9];
    const float* bih = (const float*)d_in[10];
    const float* bhh = (const float*)d_in[11];
    const float* Wm1 = (const float*)d_in[12];
    const float* bm1 = (const float*)d_in[13];
    const float* Wm2 = (const float*)d_in[14];
    const float* bm2 = (const float*)d_in[15];
    const float* Wm3 = (const float*)d_in[16];
    const float* bm3 = (const float*)d_in[17];
    float* out = (float*)d_out;

#define SYM(v, s) cudaGetSymbolAddress((void**)&v, s)
    half *Hd, *P1, *P2, *X, *H0, *t1, *t2, *L;
    half *Wcat, *Wd1h, *Wd2h, *Wd3h, *Wm1h, *Wm2h, *Wm3h;
    float *h32a, *h32b, *biascat;
    SYM(Hd, g_Hd); SYM(P1, g_P1); SYM(P2, g_P2); SYM(X, g_X);
    SYM(H0, g_H0); SYM(t1, g_t1); SYM(t2, g_t2); SYM(L, g_L);
    SYM(Wcat, g_Wcat);
    SYM(Wd1h, g_Wd1); SYM(Wd2h, g_Wd2); SYM(Wd3h, g_Wd3);
    SYM(Wm1h, g_Wm1); SYM(Wm2h, g_Wm2); SYM(Wm3h, g_Wm3);
    SYM(h32a, g_h32a); SYM(h32b, g_h32b); SYM(biascat, g_biascat);
#undef SYM

    const long M2 = (long)(LL - 1) * BB;  // 520192
    constexpr int SM128 = 2 * (128 * 72 * 2 + 128 * 72 * 2);   // 73728
    constexpr int SM64  = 2 * (128 * 72 * 2 + 64 * 72 * 2);    // 55296
    cudaFuncSetAttribute(mma_gemm<128, 1>, cudaFuncAttributeMaxDynamicSharedMemorySize, SM128);
    cudaFuncSetAttribute(mma_gemm<128, 2>, cudaFuncAttributeMaxDynamicSharedMemorySize, SM128);
    cudaFuncSetAttribute(mma_gemm<128, 4>, cudaFuncAttributeMaxDynamicSharedMemorySize, SM128);
    cudaFuncSetAttribute(mma_gemm<64, 1>,  cudaFuncAttributeMaxDynamicSharedMemorySize, SM64);
    cudaFuncSetAttribute(mma_gemm<64, 3>,  cudaFuncAttributeMaxDynamicSharedMemorySize, SM64);

    // ---- setup (ordered so the 4th launch is a REAL gates GEMM for ncu) ----
    build_X<<<(int)((M2 * AA) / 256), 256>>>(target, X);                         // 1
    build_wcat<<<(NGT * KGT + 255) / 256, 256>>>(Wih, Whh, Wcat);                // 2
    build_biascat<<<(NGT + 255) / 256, 256>>>(bih, bhh, biascat);                // 3
    // 4: dummy gates GEMM (profiling target). Inputs deterministic; outputs
    // (Hd slot0, h32b) are rewritten by the real t=1 step before consumption.
    mma_gemm<128, 4><<<dim3(NGT / 128, BB / 128), 256, SM128>>>(
        H0, HH, X, AA, AA, Wcat, KGT, biascat,
        nullptr, HH, Hd, h32a, h32b);

    fill_bos_out<<<(BB * AA) / 256, 256>>>(out);
    tohalf<<<(BB * LAT + 255) / 256, 256>>>(latent, L, BB * LAT);
    tohalf<<<(HH * LAT + 255) / 256, 256>>>(Wd1, Wd1h, HH * LAT);
    tohalf<<<(HH * HH + 255) / 256, 256>>>(Wd2, Wd2h, HH * HH);
    tohalf<<<(HH * HH + 255) / 256, 256>>>(Wd3, Wd3h, HH * HH);
    tohalf<<<(HH * HH + 255) / 256, 256>>>(Wm1, Wm1h, HH * HH);
    tohalf<<<(AA * HH + 255) / 256, 256>>>(Wm2, Wm2h, AA * HH);
    tohalf<<<(AA * AA + 255) / 256, 256>>>(Wm3, Wm3h, AA * AA);

    // ---- h0 = Wd3(tanh(Wd2(tanh(Wd1(latent))))) ----
    mma_gemm<128, 1><<<dim3(HH / 128, BB / 128), 256, SM128>>>(
        L, LAT, nullptr, 0, 0, Wd1h, LAT, bd1,
        nullptr, HH, t1, nullptr, nullptr);
    mma_gemm<128, 1><<<dim3(HH / 128, BB / 128), 256, SM128>>>(
        t1, HH, nullptr, 0, 0, Wd2h, HH, bd2,
        nullptr, HH, t2, nullptr, nullptr);
    mma_gemm<128, 2><<<dim3(HH / 128, BB / 128), 256, SM128>>>(
        t2, HH, nullptr, 0, 0, Wd3h, HH, bd3,
        h32a, HH, H0, nullptr, nullptr);

    // ---- sequential GRU: one fused gemm+gate launch per step ----
    float* hp32 = h32a;
    float* hn32 = h32b;
    for (int t = 1; t < LL; ++t) {
        const half* hin = (t == 1) ? H0 : Hd + (size_t)(t - 2) * BB * HH;
        mma_gemm<128, 4><<<dim3(NGT / 128, BB / 128), 256, SM128>>>(
            hin, HH,
            X + (size_t)(t - 1) * BB * AA, AA, AA,
            Wcat, KGT, biascat,
            nullptr, HH,
            Hd + (size_t)(t - 1) * BB * HH,
            hp32, hn32);
        float* tmp = hp32; hp32 = hn32; hn32 = tmp;
    }

    // ---- per-step decoder over all 127 steps at once ----
    mma_gemm<128, 1><<<dim3(HH / 128, (int)(M2 / 128)), 256, SM128>>>(
        Hd, HH, nullptr, 0, 0, Wm1h, HH, bm1,
        nullptr, HH, P1, nullptr, nullptr);
    mma_gemm<64, 1><<<dim3(1, (int)(M2 / 128)), 256, SM64>>>(
        P1, HH, nullptr, 0, 0, Wm2h, HH, bm2,
        nullptr, AA, P2, nullptr, nullptr);
    mma_gemm<64, 3><<<dim3(1, (int)(M2 / 128)), 256, SM64>>>(
        P2, AA, nullptr, 0, 0, Wm3h, AA, bm3,
        out, 0, nullptr, nullptr, nullptr);
}

// round 10
// speedup vs baseline: 5.9498x; 1.1921x over previous
#include <cuda_runtime.h>
#include <cuda_fp16.h>
#include <math.h>
#include <stdint.h>

#define BB 4096
#define LAT 256
#define HH 512
#define AA 64
#define LL 128
#define NG3 1536         // gate layout: 64 groups x [r8|z8|n8]
#define M2 ((long)(LL - 1) * BB)   // 520192

// ---- scratch (static device globals; ~2.9 GB) ----
__device__ half  g_Hd[(size_t)(LL - 1) * BB * HH];     // h_t fp16, slots t=1..127
__device__ half  g_P1[(size_t)(LL - 1) * BB * HH];
__device__ half  g_P2[(size_t)(LL - 1) * BB * AA];
__device__ half  g_X[(size_t)(LL - 1) * BB * AA];
__device__ half  g_Gx[(size_t)(LL - 1) * BB * NG3];    // precomputed x-gates (+bias), fp16
__device__ float g_h32a[(size_t)BB * HH];
__device__ float g_h32b[(size_t)BB * HH];
__device__ half  g_H0[(size_t)BB * HH];
__device__ half  g_t1[(size_t)BB * HH];
__device__ half  g_t2[(size_t)BB * HH];
__device__ half  g_L[(size_t)BB * LAT];
__device__ half  g_Wh3[(size_t)NG3 * HH];              // interleaved Whh
__device__ half  g_Wix[(size_t)NG3 * AA];              // interleaved Wih (r,z,nx)
__device__ half  g_Wd1[HH * LAT];
__device__ half  g_Wd2[HH * HH];
__device__ half  g_Wd3[HH * HH];
__device__ half  g_Wm1[HH * HH];
__device__ half  g_Wm2[AA * HH];
__device__ half  g_Wm3[AA * AA];
__device__ float g_gxbias[NG3];
__device__ float g_bhhn[HH];

// ============================================================
// helpers
// ============================================================
__device__ __forceinline__ uint32_t smem_u32(const void* p) {
    uint32_t a;
    asm("{ .reg .u64 t; cvta.to.shared.u64 t, %1; cvt.u32.u64 %0, t; }" : "=r"(a) : "l"(p));
    return a;
}
__device__ __forceinline__ void cpa16(uint32_t dst, const void* src) {
    asm volatile("cp.async.cg.shared.global [%0], [%1], 16;" :: "r"(dst), "l"(src));
}
__device__ __forceinline__ void cpa_commit() {
    asm volatile("cp.async.commit_group;" ::: "memory");
}
__device__ __forceinline__ void cpa_wait1() {
    asm volatile("cp.async.wait_group 1;" ::: "memory");
}
__device__ __forceinline__ float sigf(float x) { return 1.0f / (1.0f + expf(-x)); }

__device__ __forceinline__ void mma16(float d[4], const uint32_t a[4], const uint32_t b[2]) {
    asm volatile(
        "mma.sync.aligned.m16n8k16.row.col.f32.f16.f16.f32 "
        "{%0,%1,%2,%3},{%4,%5,%6,%7},{%8,%9},{%0,%1,%2,%3};"
        : "+f"(d[0]), "+f"(d[1]), "+f"(d[2]), "+f"(d[3])
        : "r"(a[0]), "r"(a[1]), "r"(a[2]), "r"(a[3]), "r"(b[0]), "r"(b[1]));
}
__device__ __forceinline__ void ldsm_x4(uint32_t r[4], uint32_t addr) {
    asm volatile("ldmatrix.sync.aligned.m8n8.x4.shared.b16 {%0,%1,%2,%3}, [%4];"
                 : "=r"(r[0]), "=r"(r[1]), "=r"(r[2]), "=r"(r[3]) : "r"(addr));
}
__device__ __forceinline__ void ldsm_x2(uint32_t r[2], uint32_t addr) {
    asm volatile("ldmatrix.sync.aligned.m8n8.x2.shared.b16 {%0,%1}, [%2];"
                 : "=r"(r[0]), "=r"(r[1]) : "r"(addr));
}

// ============================================================
// Setup kernels
// ============================================================
__global__ void fill_bos_out(float* __restrict__ out) {
    int idx = blockIdx.x * blockDim.x + threadIdx.x;   // [0, BB*AA)
    int b = idx >> 6, a = idx & 63;
    out[(size_t)b * (LL * AA) + a] = (a == 0) ? 16.0f : -16.0f;
}
// X[(t-1)*BB + b][a] : t=1 -> bos ; t>=2 -> target[b][t-1][a]
__global__ void build_X(const float* __restrict__ target, half* __restrict__ X) {
    size_t idx = (size_t)blockIdx.x * blockDim.x + threadIdx.x;
    int a = (int)(idx & 63);
    size_t row = idx >> 6;
    int trow = (int)(row >> 12);
    int b = (int)(row & 4095);
    float v;
    if (trow == 0) v = (a == 0) ? 16.0f : -16.0f;
    else           v = target[((size_t)b << 13) + (size_t)trow * AA + a];
    X[idx] = __float2half_rn(v);
}
__global__ void tohalf(const float* __restrict__ src, half* __restrict__ dst, int n) {
    int i = blockIdx.x * blockDim.x + threadIdx.x;
    if (i < n) dst[i] = __float2half_rn(src[i]);
}
// Wh3[c][k] (c in [0,1536), k in [0,512)): group g=c/24, type=(c%24)/8,
// j=8g+(c%8); row = Whh[type*512 + j]
__global__ void build_Wh3(const float* __restrict__ Whh, half* __restrict__ w) {
    int i = blockIdx.x * blockDim.x + threadIdx.x;     // [0, NG3*HH)
    if (i >= NG3 * HH) return;
    int k = i & 511, c = i >> 9;
    int g = c / 24, r = c % 24;
    int type = r >> 3, j = 8 * g + (r & 7);
    w[i] = __float2half_rn(Whh[(size_t)(type * 512 + j) * HH + k]);
}
// Wix[c][k] (k in [0,64)): same col mapping, rows from Wih (type 2 = n-gate x part)
__global__ void build_Wix(const float* __restrict__ Wih, half* __restrict__ w) {
    int i = blockIdx.x * blockDim.x + threadIdx.x;     // [0, NG3*AA)
    if (i >= NG3 * AA) return;
    int k = i & 63, c = i >> 6;
    int g = c / 24, r = c % 24;
    int type = r >> 3, j = 8 * g + (r & 7);
    w[i] = __float2half_rn(Wih[(type * 512 + j) * AA + k]);
}
// gxbias: r: bih+bhh ; z: bih+bhh ; nx: bih only (bhh_n applied in step epilogue)
__global__ void build_gxbias(const float* __restrict__ bih, const float* __restrict__ bhh,
                             float* __restrict__ bc) {
    int c = blockIdx.x * blockDim.x + threadIdx.x;
    if (c >= NG3) return;
    int g = c / 24, r = c % 24;
    int type = r >> 3, j = 8 * g + (r & 7);
    float v;
    if (type == 0)      v = bih[j] + bhh[j];
    else if (type == 1) v = bih[512 + j] + bhh[512 + j];
    else                v = bih[1024 + j];
    bc[c] = v;
}
__global__ void build_bhhn(const float* __restrict__ bhh, float* __restrict__ bn) {
    int j = blockIdx.x * blockDim.x + threadIdx.x;
    if (j < HH) bn[j] = bhh[1024 + j];
}

// ============================================================
// Generic fp16 GEMM: C = epi(A[M,K] @ W[N,K]^T + bias), fp32 accum.
// BM=128, BN in {128,64}, BK=64, 256 threads, 2 CTAs/SM,
// 3-stage cp.async pipeline (ONE __syncthreads per chunk), ldmatrix.
// EPI: 0 = fp16 store; 1 = tanh -> fp16; 2 = f32 + fp16;
//      3 = scatter f32 out[b][t][n].
// ============================================================
template <int BN, int EPI>
__global__ void __launch_bounds__(256, 2)
mma_gemm(const half* __restrict__ A_g, long lda,
         const half* __restrict__ B_g, int K,
         const float* __restrict__ bias,
         float* __restrict__ Cf, long ldc,
         half* __restrict__ Ch)
{
    constexpr int SS = 72;
    constexpr int WARPS_M = (BN == 128) ? 2 : 4;
    constexpr int WM = 128 / WARPS_M;
    constexpr int MI = WM / 16;
    constexpr int NI = 4;
    constexpr int ABYT = 128 * SS * 2;
    constexpr int BBYT = BN * SS * 2;
    constexpr int BUF = ABYT + BBYT;

    extern __shared__ char smem[];
    const uint32_t sb = smem_u32(smem);

    const int tid = threadIdx.x;
    const int wid = tid >> 5, lane = tid & 31;
    const int wm = wid % WARPS_M, wn = wid / WARPS_M;
    const int gr = lane >> 2, tq = lane & 3;
    const int aro = (lane & 7) + ((lane >> 3) & 1) * 8;
    const int aco = (lane >> 4) * 8;
    const int bro = ((lane >> 4) & 1) * 8 + (lane & 7);
    const int bko = ((lane >> 3) & 1) * 8;

    const long m0 = (long)blockIdx.y * 128;
    const int  n0 = blockIdx.x * BN;
    const int  nc = K >> 6;

    float acc[MI][NI][4];
#pragma unroll
    for (int mi = 0; mi < MI; ++mi)
#pragma unroll
        for (int ni = 0; ni < NI; ++ni)
#pragma unroll
            for (int q = 0; q < 4; ++q) acc[mi][ni][q] = 0.0f;

    auto load_chunk = [&](int ch) {
        const int k0 = ch << 6;
        const uint32_t base = sb + (ch % 3) * BUF;
#pragma unroll
        for (int it = 0; it < 4; ++it) {
            int e = tid + it * 256;
            int row = e >> 3, seg = e & 7;
            cpa16(base + (uint32_t)(row * SS + seg * 8) * 2,
                  A_g + (m0 + row) * lda + k0 + seg * 8);
        }
#pragma unroll
        for (int it = 0; it < BN / 32; ++it) {
            int e = tid + it * 256;
            int row = e >> 3, seg = e & 7;
            cpa16(base + ABYT + (uint32_t)(row * SS + seg * 8) * 2,
                  B_g + (long)(n0 + row) * K + k0 + seg * 8);
        }
    };

    load_chunk(0); cpa_commit();
    if (nc > 1) load_chunk(1);
    cpa_commit();

    for (int ch = 0; ch < nc; ++ch) {
        cpa_wait1();                 // chunk ch resident
        __syncthreads();             // all warps done with buf (ch+2)%3 == (ch-1)%3
        if (ch + 2 < nc) load_chunk(ch + 2);
        cpa_commit();

        const uint32_t aBase = sb + (ch % 3) * BUF;
        const uint32_t bBase = aBase + ABYT;

#pragma unroll
        for (int k16 = 0; k16 < 4; ++k16) {
            const int kk = k16 * 16;
            uint32_t af[MI][4], bf[NI][2];
#pragma unroll
            for (int mi = 0; mi < MI; ++mi)
                ldsm_x4(af[mi], aBase + (uint32_t)((wm * WM + mi * 16 + aro) * SS + kk + aco) * 2);
#pragma unroll
            for (int n2 = 0; n2 < NI / 2; ++n2)
                ldsm_x4(&bf[2 * n2][0], bBase + (uint32_t)((wn * 32 + n2 * 16 + bro) * SS + kk + bko) * 2);
#pragma unroll
            for (int mi = 0; mi < MI; ++mi)
#pragma unroll
                for (int ni = 0; ni < NI; ++ni)
                    mma16(acc[mi][ni], af[mi], bf[ni]);
        }
    }

    // ---- epilogue ----
#pragma unroll
    for (int mi = 0; mi < MI; ++mi) {
#pragma unroll
        for (int ni = 0; ni < NI; ++ni) {
            const int col = n0 + wn * 32 + ni * 8 + 2 * tq;
            const long mA = m0 + wm * WM + mi * 16 + gr;
            float2 bc = *(const float2*)(bias + col);
            float v0 = acc[mi][ni][0] + bc.x;
            float v1 = acc[mi][ni][1] + bc.y;
            float v2 = acc[mi][ni][2] + bc.x;
            float v3 = acc[mi][ni][3] + bc.y;

            if (EPI <= 2) {
                if (EPI == 1) { v0 = tanhf(v0); v1 = tanhf(v1); v2 = tanhf(v2); v3 = tanhf(v3); }
                if (EPI == 2) {
                    *(float2*)(Cf + mA * ldc + col) = make_float2(v0, v1);
                    *(float2*)(Cf + (mA + 8) * ldc + col) = make_float2(v2, v3);
                }
                __half2 p0 = __floats2half2_rn(v0, v1);
                __half2 p1 = __floats2half2_rn(v2, v3);
                *(uint32_t*)(Ch + mA * ldc + col) = *(uint32_t*)&p0;
                *(uint32_t*)(Ch + (mA + 8) * ldc + col) = *(uint32_t*)&p1;
            } else {  // EPI == 3 scatter
                long t1_ = (mA >> 12) + 1, b1_ = mA & 4095;
                long t2_ = ((mA + 8) >> 12) + 1, b2_ = (mA + 8) & 4095;
                *(float2*)(Cf + b1_ * (LL * AA) + t1_ * AA + col) = make_float2(v0, v1);
                *(float2*)(Cf + b2_ * (LL * AA) + t2_ * AA + col) = make_float2(v2, v3);
            }
        }
    }
}

// ============================================================
// GRU step GEMM: Ghh = h @ Wh3^T (N=1536, K=512), fused gate epilogue.
// BM=128, BN=96 (4 N-warps x 24 cols = [r8|z8|n8] per 8-j group),
// NI=3 so each thread owns r,z,nh for the SAME (row, j). nx + biases
// come from precomputed Gx (fp16).
// ============================================================
__global__ void __launch_bounds__(256, 2)
gru_gemm(const half* __restrict__ A_g,      // hprev fp16 [BB,512]
         const half* __restrict__ B_g,      // Wh3 [1536,512]
         const half* __restrict__ gx,       // Gx slice [BB,1536]
         const float* __restrict__ bhhn,    // [512]
         const float* __restrict__ hprev32,
         float* __restrict__ hnew32,
         half* __restrict__ hnew16)
{
    constexpr int SS = 72;
    constexpr int BN = 96;
    constexpr int MI = 4;                   // WM=64, 2 M-warps
    constexpr int NI = 3;
    constexpr int ABYT = 128 * SS * 2;
    constexpr int BBYT = BN * SS * 2;
    constexpr int BUF = ABYT + BBYT;
    constexpr int K = HH;
    constexpr int nc = K >> 6;              // 8

    extern __shared__ char smem[];
    const uint32_t sb = smem_u32(smem);

    const int tid = threadIdx.x;
    const int wid = tid >> 5, lane = tid & 31;
    const int wm = wid & 1, wn = wid >> 1;  // 2 x 4
    const int gr = lane >> 2, tq = lane & 3;
    const int aro = (lane & 7) + ((lane >> 3) & 1) * 8;
    const int aco = (lane >> 4) * 8;
    const int bro = ((lane >> 4) & 1) * 8 + (lane & 7);
    const int bko = ((lane >> 3) & 1) * 8;
    const int b2ro = 16 + (lane & 7);
    const int b2ko = ((lane >> 3) & 1) * 8;

    const long m0 = (long)blockIdx.y * 128;
    const int  n0 = blockIdx.x * BN;

    float acc[MI][NI][4];
#pragma unroll
    for (int mi = 0; mi < MI; ++mi)
#pragma unroll
        for (int ni = 0; ni < NI; ++ni)
#pragma unroll
            for (int q = 0; q < 4; ++q) acc[mi][ni][q] = 0.0f;

    auto load_chunk = [&](int ch) {
        const int k0 = ch << 6;
        const uint32_t base = sb + (ch % 3) * BUF;
#pragma unroll
        for (int it = 0; it < 4; ++it) {
            int e = tid + it * 256;
            int row = e >> 3, seg = e & 7;
            cpa16(base + (uint32_t)(row * SS + seg * 8) * 2,
                  A_g + (m0 + row) * (long)HH + k0 + seg * 8);
        }
#pragma unroll
        for (int it = 0; it < 3; ++it) {
            int e = tid + it * 256;
            int row = e >> 3, seg = e & 7;
            cpa16(base + ABYT + (uint32_t)(row * SS + seg * 8) * 2,
                  B_g + (long)(n0 + row) * K + k0 + seg * 8);
        }
    };

    load_chunk(0); cpa_commit();
    load_chunk(1); cpa_commit();

    for (int ch = 0; ch < nc; ++ch) {
        cpa_wait1();
        __syncthreads();
        if (ch + 2 < nc) load_chunk(ch + 2);
        cpa_commit();

        const uint32_t aBase = sb + (ch % 3) * BUF;
        const uint32_t bBase = aBase + ABYT;

#pragma unroll
        for (int k16 = 0; k16 < 4; ++k16) {
            const int kk = k16 * 16;
            uint32_t af[MI][4], bf[NI][2];
#pragma unroll
            for (int mi = 0; mi < MI; ++mi)
                ldsm_x4(af[mi], aBase + (uint32_t)((wm * 64 + mi * 16 + aro) * SS + kk + aco) * 2);
            ldsm_x4(&bf[0][0], bBase + (uint32_t)((wn * 24 + bro) * SS + kk + bko) * 2);
            ldsm_x2(&bf[2][0], bBase + (uint32_t)((wn * 24 + b2ro) * SS + kk + b2ko) * 2);
#pragma unroll
            for (int mi = 0; mi < MI; ++mi)
#pragma unroll
                for (int ni = 0; ni < NI; ++ni)
                    mma16(acc[mi][ni], af[mi], bf[ni]);
        }
    }

    // ---- fused GRU epilogue (no shuffles) ----
    const int jb = 8 * (4 * blockIdx.x + wn);   // this warp's 8-j group base
    const int j0 = jb + 2 * tq;
    const float2 bn2 = *(const float2*)(bhhn + j0);

#pragma unroll
    for (int mi = 0; mi < MI; ++mi) {
#pragma unroll
        for (int h2 = 0; h2 < 2; ++h2) {
            const long m = m0 + wm * 64 + mi * 16 + gr + h2 * 8;
            const half* gp = gx + m * NG3 + n0 + wn * 24 + 2 * tq;
            float2 gxr = __half22float2(*(const __half2*)(gp));
            float2 gxz = __half22float2(*(const __half2*)(gp + 8));
            float2 gxn = __half22float2(*(const __half2*)(gp + 16));
            float2 hp = *(const float2*)(hprev32 + m * HH + j0);
            const int q0 = h2 * 2, q1 = q0 + 1;

            float r0 = sigf(acc[mi][0][q0] + gxr.x);
            float r1 = sigf(acc[mi][0][q1] + gxr.y);
            float z0 = sigf(acc[mi][1][q0] + gxz.x);
            float z1 = sigf(acc[mi][1][q1] + gxz.y);
            float nv0 = tanhf(gxn.x + r0 * (acc[mi][2][q0] + bn2.x));
            float nv1 = tanhf(gxn.y + r1 * (acc[mi][2][q1] + bn2.y));
            float h0 = (1.0f - z0) * nv0 + z0 * hp.x;
            float h1 = (1.0f - z1) * nv1 + z1 * hp.y;

            *(float2*)(hnew32 + m * HH + j0) = make_float2(h0, h1);
            __half2 ph = __floats2half2_rn(h0, h1);
            *(uint32_t*)(hnew16 + m * HH + j0) = *(uint32_t*)&ph;
        }
    }
}

// ============================================================
// Orchestration
// ============================================================
extern "C" void kernel_launch(void* const* d_in, const int* in_sizes, int n_in,
                              void* d_out, int out_size)
{
    const float* latent = (const float*)d_in[0];
    const float* target = (const float*)d_in[1];
    const float* Wd1 = (const float*)d_in[2];
    const float* bd1 = (const float*)d_in[3];
    const float* Wd2 = (const float*)d_in[4];
    const float* bd2 = (const float*)d_in[5];
    const float* Wd3 = (const float*)d_in[6];
    const float* bd3 = (const float*)d_in[7];
    const float* Wih = (const float*)d_in[8];
    const float* Whh = (const float*)d_in[9];
    const float* bih = (const float*)d_in[10];
    const float* bhh = (const float*)d_in[11];
    const float* Wm1 = (const float*)d_in[12];
    const float* bm1 = (const float*)d_in[13];
    const float* Wm2 = (const float*)d_in[14];
    const float* bm2 = (const float*)d_in[15];
    const float* Wm3 = (const float*)d_in[16];
    const float* bm3 = (const float*)d_in[17];
    float* out = (float*)d_out;

#define SYM(v, s) cudaGetSymbolAddress((void**)&v, s)
    half *Hd, *P1, *P2, *X, *Gx, *H0, *t1, *t2, *L;
    half *Wh3, *Wix, *Wd1h, *Wd2h, *Wd3h, *Wm1h, *Wm2h, *Wm3h;
    float *h32a, *h32b, *gxbias, *bhhn;
    SYM(Hd, g_Hd); SYM(P1, g_P1); SYM(P2, g_P2); SYM(X, g_X); SYM(Gx, g_Gx);
    SYM(H0, g_H0); SYM(t1, g_t1); SYM(t2, g_t2); SYM(L, g_L);
    SYM(Wh3, g_Wh3); SYM(Wix, g_Wix);
    SYM(Wd1h, g_Wd1); SYM(Wd2h, g_Wd2); SYM(Wd3h, g_Wd3);
    SYM(Wm1h, g_Wm1); SYM(Wm2h, g_Wm2); SYM(Wm3h, g_Wm3);
    SYM(h32a, g_h32a); SYM(h32b, g_h32b); SYM(gxbias, g_gxbias); SYM(bhhn, g_bhhn);
#undef SYM

    constexpr int SM128 = 3 * (128 * 72 * 2 + 128 * 72 * 2);   // 110592
    constexpr int SM64  = 3 * (128 * 72 * 2 + 64 * 72 * 2);    // 82944
    constexpr int SMGRU = 3 * (128 * 72 * 2 + 96 * 72 * 2);    // 96768
    cudaFuncSetAttribute(mma_gemm<128, 0>, cudaFuncAttributeMaxDynamicSharedMemorySize, SM128);
    cudaFuncSetAttribute(mma_gemm<128, 1>, cudaFuncAttributeMaxDynamicSharedMemorySize, SM128);
    cudaFuncSetAttribute(mma_gemm<128, 2>, cudaFuncAttributeMaxDynamicSharedMemorySize, SM128);
    cudaFuncSetAttribute(mma_gemm<64, 1>,  cudaFuncAttributeMaxDynamicSharedMemorySize, SM64);
    cudaFuncSetAttribute(mma_gemm<64, 3>,  cudaFuncAttributeMaxDynamicSharedMemorySize, SM64);
    cudaFuncSetAttribute(gru_gemm,         cudaFuncAttributeMaxDynamicSharedMemorySize, SMGRU);

    // ---- setup (4th launch = real gru_gemm for ncu profiling) ----
    build_X<<<(int)((M2 * AA) / 256), 256>>>(target, X);                       // 1
    build_Wh3<<<(NG3 * HH + 255) / 256, 256>>>(Whh, Wh3);                      // 2
    build_bhhn<<<(HH + 255) / 256, 256>>>(bhh, bhhn);                          // 3
    // 4: dummy gru step (profiling target). All inputs deterministic per
    // replay; outputs (Hd slot0, h32b) fully rewritten by real t=1 step.
    gru_gemm<<<dim3(NG3 / 96, BB / 128), 256, SMGRU>>>(
        H0, Wh3, Gx, bhhn, h32a, h32b, Hd);

    build_Wix<<<(NG3 * AA + 255) / 256, 256>>>(Wih, Wix);
    build_gxbias<<<(NG3 + 255) / 256, 256>>>(bih, bhh, gxbias);
    fill_bos_out<<<(BB * AA) / 256, 256>>>(out);
    tohalf<<<(BB * LAT + 255) / 256, 256>>>(latent, L, BB * LAT);
    tohalf<<<(HH * LAT + 255) / 256, 256>>>(Wd1, Wd1h, HH * LAT);
    tohalf<<<(HH * HH + 255) / 256, 256>>>(Wd2, Wd2h, HH * HH);
    tohalf<<<(HH * HH + 255) / 256, 256>>>(Wd3, Wd3h, HH * HH);
    tohalf<<<(HH * HH + 255) / 256, 256>>>(Wm1, Wm1h, HH * HH);
    tohalf<<<(AA * HH + 255) / 256, 256>>>(Wm2, Wm2h, AA * HH);
    tohalf<<<(AA * AA + 255) / 256, 256>>>(Wm3, Wm3h, AA * AA);

    // ---- precompute all x-gates: Gx = X @ Wix^T + gxbias  [M2, 1536] fp16 ----
    mma_gemm<128, 0><<<dim3(NG3 / 128, (int)(M2 / 128)), 256, SM128>>>(
        X, AA, Wix, AA, gxbias, nullptr, NG3, Gx);

    // ---- h0 = Wd3(tanh(Wd2(tanh(Wd1(latent))))) ----
    mma_gemm<128, 1><<<dim3(HH / 128, BB / 128), 256, SM128>>>(
        L, LAT, Wd1h, LAT, bd1, nullptr, HH, t1);
    mma_gemm<128, 1><<<dim3(HH / 128, BB / 128), 256, SM128>>>(
        t1, HH, Wd2h, HH, bd2, nullptr, HH, t2);
    mma_gemm<128, 2><<<dim3(HH / 128, BB / 128), 256, SM128>>>(
        t2, HH, Wd3h, HH, bd3, h32a, HH, H0);

    // ---- sequential GRU: one fused launch per step ----
    float* hp32 = h32a;
    float* hn32 = h32b;
    for (int t = 1; t < LL; ++t) {
        const half* hin = (t == 1) ? H0 : Hd + (size_t)(t - 2) * BB * HH;
        gru_gemm<<<dim3(NG3 / 96, BB / 128), 256, SMGRU>>>(
            hin, Wh3,
            Gx + (size_t)(t - 1) * BB * NG3,
            bhhn, hp32, hn32,
            Hd + (size_t)(t - 1) * BB * HH);
        float* tmp = hp32; hp32 = hn32; hn32 = tmp;
    }

    // ---- per-step decoder over all 127 steps at once ----
    mma_gemm<128, 1><<<dim3(HH / 128, (int)(M2 / 128)), 256, SM128>>>(
        Hd, HH, Wm1h, HH, bm1, nullptr, HH, P1);
    mma_gemm<64, 1><<<dim3(1, (int)(M2 / 128)), 256, SM64>>>(
        P1, HH, Wm2h, HH, bm2, nullptr, AA, P2);
    mma_gemm<64, 3><<<dim3(1, (int)(M2 / 128)), 256, SM64>>>(
        P2, AA, Wm3h, AA, bm3, out, 0, nullptr);
}

// round 11
// speedup vs baseline: 6.1314x; 1.0305x over previous
#include <cuda_runtime.h>
#include <cuda_fp16.h>
#include <math.h>
#include <stdint.h>

#define BB 4096
#define LAT 256
#define HH 512
#define AA 64
#define LL 128
#define NG3 1536         // gate layout: 64 groups x [r8|z8|n8]
#define M2 ((long)(LL - 1) * BB)   // 520192

// ---- scratch (static device globals; ~2.9 GB) ----
__device__ half  g_Hd[(size_t)(LL - 1) * BB * HH];     // h_t fp16, slots t=1..127
__device__ half  g_P1[(size_t)(LL - 1) * BB * HH];
__device__ half  g_P2[(size_t)(LL - 1) * BB * AA];
__device__ half  g_X[(size_t)(LL - 1) * BB * AA];
__device__ half  g_Gx[(size_t)(LL - 1) * BB * NG3];    // precomputed x-gates (+bias)
__device__ float g_h32a[(size_t)BB * HH];
__device__ float g_h32b[(size_t)BB * HH];
__device__ half  g_H0[(size_t)BB * HH];
__device__ half  g_t1[(size_t)BB * HH];
__device__ half  g_t2[(size_t)BB * HH];
__device__ half  g_L[(size_t)BB * LAT];
__device__ half  g_Wh3[(size_t)NG3 * HH];              // interleaved Whh
__device__ half  g_Wix[(size_t)NG3 * AA];              // interleaved Wih (r,z,nx)
__device__ half  g_Wd1[HH * LAT];
__device__ half  g_Wd2[HH * HH];
__device__ half  g_Wd3[HH * HH];
__device__ half  g_Wm1[HH * HH];
__device__ half  g_Wm2[AA * HH];
__device__ half  g_Wm3[AA * AA];
__device__ float g_gxbias[NG3];
__device__ float g_bhhn[HH];

// ============================================================
// helpers
// ============================================================
__device__ __forceinline__ uint32_t smem_u32(const void* p) {
    uint32_t a;
    asm("{ .reg .u64 t; cvta.to.shared.u64 t, %1; cvt.u32.u64 %0, t; }" : "=r"(a) : "l"(p));
    return a;
}
__device__ __forceinline__ void cpa16(uint32_t dst, const void* src) {
    asm volatile("cp.async.cg.shared.global [%0], [%1], 16;" :: "r"(dst), "l"(src));
}
__device__ __forceinline__ void cpa_commit() {
    asm volatile("cp.async.commit_group;" ::: "memory");
}
__device__ __forceinline__ void cpa_wait1() {
    asm volatile("cp.async.wait_group 1;" ::: "memory");
}
__device__ __forceinline__ float sigf(float x) { return 1.0f / (1.0f + expf(-x)); }

__device__ __forceinline__ void mma16(float d[4], const uint32_t a[4], const uint32_t b[2]) {
    asm volatile(
        "mma.sync.aligned.m16n8k16.row.col.f32.f16.f16.f32 "
        "{%0,%1,%2,%3},{%4,%5,%6,%7},{%8,%9},{%0,%1,%2,%3};"
        : "+f"(d[0]), "+f"(d[1]), "+f"(d[2]), "+f"(d[3])
        : "r"(a[0]), "r"(a[1]), "r"(a[2]), "r"(a[3]), "r"(b[0]), "r"(b[1]));
}
__device__ __forceinline__ void ldsm_x4(uint32_t r[4], uint32_t addr) {
    asm volatile("ldmatrix.sync.aligned.m8n8.x4.shared.b16 {%0,%1,%2,%3}, [%4];"
                 : "=r"(r[0]), "=r"(r[1]), "=r"(r[2]), "=r"(r[3]) : "r"(addr));
}
__device__ __forceinline__ void ldsm_x2(uint32_t r[2], uint32_t addr) {
    asm volatile("ldmatrix.sync.aligned.m8n8.x2.shared.b16 {%0,%1}, [%2];"
                 : "=r"(r[0]), "=r"(r[1]) : "r"(addr));
}

// ============================================================
// Setup kernels
// ============================================================
__global__ void fill_bos_out(float* __restrict__ out) {
    int idx = blockIdx.x * blockDim.x + threadIdx.x;
    int b = idx >> 6, a = idx & 63;
    out[(size_t)b * (LL * AA) + a] = (a == 0) ? 16.0f : -16.0f;
}
__global__ void build_X(const float* __restrict__ target, half* __restrict__ X) {
    size_t idx = (size_t)blockIdx.x * blockDim.x + threadIdx.x;
    int a = (int)(idx & 63);
    size_t row = idx >> 6;
    int trow = (int)(row >> 12);
    int b = (int)(row & 4095);
    float v;
    if (trow == 0) v = (a == 0) ? 16.0f : -16.0f;
    else           v = target[((size_t)b << 13) + (size_t)trow * AA + a];
    X[idx] = __float2half_rn(v);
}
__global__ void tohalf(const float* __restrict__ src, half* __restrict__ dst, int n) {
    int i = blockIdx.x * blockDim.x + threadIdx.x;
    if (i < n) dst[i] = __float2half_rn(src[i]);
}
__global__ void build_Wh3(const float* __restrict__ Whh, half* __restrict__ w) {
    int i = blockIdx.x * blockDim.x + threadIdx.x;
    if (i >= NG3 * HH) return;
    int k = i & 511, c = i >> 9;
    int g = c / 24, r = c % 24;
    int type = r >> 3, j = 8 * g + (r & 7);
    w[i] = __float2half_rn(Whh[(size_t)(type * 512 + j) * HH + k]);
}
__global__ void build_Wix(const float* __restrict__ Wih, half* __restrict__ w) {
    int i = blockIdx.x * blockDim.x + threadIdx.x;
    if (i >= NG3 * AA) return;
    int k = i & 63, c = i >> 6;
    int g = c / 24, r = c % 24;
    int type = r >> 3, j = 8 * g + (r & 7);
    w[i] = __float2half_rn(Wih[(type * 512 + j) * AA + k]);
}
__global__ void build_gxbias(const float* __restrict__ bih, const float* __restrict__ bhh,
                             float* __restrict__ bc) {
    int c = blockIdx.x * blockDim.x + threadIdx.x;
    if (c >= NG3) return;
    int g = c / 24, r = c % 24;
    int type = r >> 3, j = 8 * g + (r & 7);
    float v;
    if (type == 0)      v = bih[j] + bhh[j];
    else if (type == 1) v = bih[512 + j] + bhh[512 + j];
    else                v = bih[1024 + j];
    bc[c] = v;
}
__global__ void build_bhhn(const float* __restrict__ bhh, float* __restrict__ bn) {
    int j = blockIdx.x * blockDim.x + threadIdx.x;
    if (j < HH) bn[j] = bhh[1024 + j];
}

// ============================================================
// dec_tile: one BM=128 x BN GEMM tile, fp16 in, fp32 acc.
// m0 = GLOBAL row (into A rows and C rows / scatter mapping).
// 3-stage cp.async, ldmatrix. 256 threads.
// EPI: 0 = fp16 store; 1 = tanh->fp16; 2 = f32 + fp16; 3 = scatter f32.
// ============================================================
template <int BN, int EPI>
__device__ __forceinline__ void dec_tile(
    long m0, int n0,
    const half* __restrict__ A_g, long lda,
    const half* __restrict__ B_g, int K,
    const float* __restrict__ bias,
    float* __restrict__ Cf, long ldc,
    half* __restrict__ Ch)
{
    constexpr int SS = 72;
    constexpr int WARPS_M = (BN == 128) ? 2 : 4;
    constexpr int WM = 128 / WARPS_M;
    constexpr int MI = WM / 16;
    constexpr int NI = 4;
    constexpr int ABYT = 128 * SS * 2;
    constexpr int BBYT = BN * SS * 2;
    constexpr int BUF = ABYT + BBYT;

    extern __shared__ char smem[];
    const uint32_t sb = smem_u32(smem);

    const int tid = threadIdx.x;
    const int wid = tid >> 5, lane = tid & 31;
    const int wm = wid % WARPS_M, wn = wid / WARPS_M;
    const int gr = lane >> 2, tq = lane & 3;
    const int aro = (lane & 7) + ((lane >> 3) & 1) * 8;
    const int aco = (lane >> 4) * 8;
    const int bro = ((lane >> 4) & 1) * 8 + (lane & 7);
    const int bko = ((lane >> 3) & 1) * 8;

    const int nc = K >> 6;

    float acc[MI][NI][4];
#pragma unroll
    for (int mi = 0; mi < MI; ++mi)
#pragma unroll
        for (int ni = 0; ni < NI; ++ni)
#pragma unroll
            for (int q = 0; q < 4; ++q) acc[mi][ni][q] = 0.0f;

    auto load_chunk = [&](int ch) {
        const int k0 = ch << 6;
        const uint32_t base = sb + (ch % 3) * BUF;
#pragma unroll
        for (int it = 0; it < 4; ++it) {
            int e = tid + it * 256;
            int row = e >> 3, seg = e & 7;
            cpa16(base + (uint32_t)(row * SS + seg * 8) * 2,
                  A_g + (m0 + row) * lda + k0 + seg * 8);
        }
#pragma unroll
        for (int it = 0; it < BN / 32; ++it) {
            int e = tid + it * 256;
            int row = e >> 3, seg = e & 7;
            cpa16(base + ABYT + (uint32_t)(row * SS + seg * 8) * 2,
                  B_g + (long)(n0 + row) * K + k0 + seg * 8);
        }
    };

    load_chunk(0); cpa_commit();
    if (nc > 1) load_chunk(1);
    cpa_commit();

    for (int ch = 0; ch < nc; ++ch) {
        cpa_wait1();
        __syncthreads();
        if (ch + 2 < nc) load_chunk(ch + 2);
        cpa_commit();

        const uint32_t aBase = sb + (ch % 3) * BUF;
        const uint32_t bBase = aBase + ABYT;

#pragma unroll
        for (int k16 = 0; k16 < 4; ++k16) {
            const int kk = k16 * 16;
            uint32_t af[MI][4], bf[NI][2];
#pragma unroll
            for (int mi = 0; mi < MI; ++mi)
                ldsm_x4(af[mi], aBase + (uint32_t)((wm * WM + mi * 16 + aro) * SS + kk + aco) * 2);
#pragma unroll
            for (int n2 = 0; n2 < NI / 2; ++n2)
                ldsm_x4(&bf[2 * n2][0], bBase + (uint32_t)((wn * 32 + n2 * 16 + bro) * SS + kk + bko) * 2);
#pragma unroll
            for (int mi = 0; mi < MI; ++mi)
#pragma unroll
                for (int ni = 0; ni < NI; ++ni)
                    mma16(acc[mi][ni], af[mi], bf[ni]);
        }
    }

#pragma unroll
    for (int mi = 0; mi < MI; ++mi) {
#pragma unroll
        for (int ni = 0; ni < NI; ++ni) {
            const int col = n0 + wn * 32 + ni * 8 + 2 * tq;
            const long mA = m0 + wm * WM + mi * 16 + gr;
            float2 bc = *(const float2*)(bias + col);
            float v0 = acc[mi][ni][0] + bc.x;
            float v1 = acc[mi][ni][1] + bc.y;
            float v2 = acc[mi][ni][2] + bc.x;
            float v3 = acc[mi][ni][3] + bc.y;

            if (EPI <= 2) {
                if (EPI == 1) { v0 = tanhf(v0); v1 = tanhf(v1); v2 = tanhf(v2); v3 = tanhf(v3); }
                if (EPI == 2) {
                    *(float2*)(Cf + mA * ldc + col) = make_float2(v0, v1);
                    *(float2*)(Cf + (mA + 8) * ldc + col) = make_float2(v2, v3);
                }
                __half2 p0 = __floats2half2_rn(v0, v1);
                __half2 p1 = __floats2half2_rn(v2, v3);
                *(uint32_t*)(Ch + mA * ldc + col) = *(uint32_t*)&p0;
                *(uint32_t*)(Ch + (mA + 8) * ldc + col) = *(uint32_t*)&p1;
            } else {
                long t1_ = (mA >> 12) + 1, b1_ = mA & 4095;
                long t2_ = ((mA + 8) >> 12) + 1, b2_ = (mA + 8) & 4095;
                *(float2*)(Cf + b1_ * (LL * AA) + t1_ * AA + col) = make_float2(v0, v1);
                *(float2*)(Cf + b2_ * (LL * AA) + t2_ * AA + col) = make_float2(v2, v3);
            }
        }
    }
}

// standalone GEMM wrapper (mrow0 = global row offset)
template <int BN, int EPI>
__global__ void __launch_bounds__(256, 2)
mma_gemm(long mrow0,
         const half* __restrict__ A_g, long lda,
         const half* __restrict__ B_g, int K,
         const float* __restrict__ bias,
         float* __restrict__ Cf, long ldc,
         half* __restrict__ Ch)
{
    dec_tile<BN, EPI>(mrow0 + (long)blockIdx.y * 128, blockIdx.x * BN,
                      A_g, lda, B_g, K, bias, Cf, ldc, Ch);
}

// ============================================================
// gru_tile: one 128x96 tile of Ghh = h @ Wh3^T + fused GRU epilogue
// ============================================================
__device__ __forceinline__ void gru_tile(
    const half* __restrict__ A_g,      // hprev fp16 [BB,512]
    const half* __restrict__ gx,       // Gx slab [BB,1536]
    const float* __restrict__ hprev32,
    float* __restrict__ hnew32,
    half* __restrict__ hnew16,
    int mbk, int nbk)
{
    constexpr int SS = 72;
    constexpr int BN = 96;
    constexpr int MI = 4;
    constexpr int NI = 3;
    constexpr int ABYT = 128 * SS * 2;
    constexpr int BBYT = BN * SS * 2;
    constexpr int BUF = ABYT + BBYT;
    constexpr int nc = HH >> 6;

    extern __shared__ char smem[];
    const uint32_t sb = smem_u32(smem);

    const int tid = threadIdx.x;
    const int wid = tid >> 5, lane = tid & 31;
    const int wm = wid & 1, wn = wid >> 1;
    const int gr = lane >> 2, tq = lane & 3;
    const int aro = (lane & 7) + ((lane >> 3) & 1) * 8;
    const int aco = (lane >> 4) * 8;
    const int bro = ((lane >> 4) & 1) * 8 + (lane & 7);
    const int bko = ((lane >> 3) & 1) * 8;
    const int b2ro = 16 + (lane & 7);
    const int b2ko = ((lane >> 3) & 1) * 8;

    const long m0 = (long)mbk * 128;
    const int  n0 = nbk * 96;
    const half* B_g = g_Wh3;

    float acc[MI][NI][4];
#pragma unroll
    for (int mi = 0; mi < MI; ++mi)
#pragma unroll
        for (int ni = 0; ni < NI; ++ni)
#pragma unroll
            for (int q = 0; q < 4; ++q) acc[mi][ni][q] = 0.0f;

    auto load_chunk = [&](int ch) {
        const int k0 = ch << 6;
        const uint32_t base = sb + (ch % 3) * BUF;
#pragma unroll
        for (int it = 0; it < 4; ++it) {
            int e = tid + it * 256;
            int row = e >> 3, seg = e & 7;
            cpa16(base + (uint32_t)(row * SS + seg * 8) * 2,
                  A_g + (m0 + row) * (long)HH + k0 + seg * 8);
        }
#pragma unroll
        for (int it = 0; it < 3; ++it) {
            int e = tid + it * 256;
            int row = e >> 3, seg = e & 7;
            cpa16(base + ABYT + (uint32_t)(row * SS + seg * 8) * 2,
                  B_g + (long)(n0 + row) * HH + k0 + seg * 8);
        }
    };

    load_chunk(0); cpa_commit();
    load_chunk(1); cpa_commit();

    for (int ch = 0; ch < nc; ++ch) {
        cpa_wait1();
        __syncthreads();
        if (ch + 2 < nc) load_chunk(ch + 2);
        cpa_commit();

        const uint32_t aBase = sb + (ch % 3) * BUF;
        const uint32_t bBase = aBase + ABYT;

#pragma unroll
        for (int k16 = 0; k16 < 4; ++k16) {
            const int kk = k16 * 16;
            uint32_t af[MI][4], bf[NI][2];
#pragma unroll
            for (int mi = 0; mi < MI; ++mi)
                ldsm_x4(af[mi], aBase + (uint32_t)((wm * 64 + mi * 16 + aro) * SS + kk + aco) * 2);
            ldsm_x4(&bf[0][0], bBase + (uint32_t)((wn * 24 + bro) * SS + kk + bko) * 2);
            ldsm_x2(&bf[2][0], bBase + (uint32_t)((wn * 24 + b2ro) * SS + kk + b2ko) * 2);
#pragma unroll
            for (int mi = 0; mi < MI; ++mi)
#pragma unroll
                for (int ni = 0; ni < NI; ++ni)
                    mma16(acc[mi][ni], af[mi], bf[ni]);
        }
    }

    const int jb = 8 * (4 * nbk + wn);
    const int j0 = jb + 2 * tq;
    const float2 bn2 = *(const float2*)(g_bhhn + j0);

#pragma unroll
    for (int mi = 0; mi < MI; ++mi) {
#pragma unroll
        for (int h2 = 0; h2 < 2; ++h2) {
            const long m = m0 + wm * 64 + mi * 16 + gr + h2 * 8;
            const half* gp = gx + m * NG3 + n0 + wn * 24 + 2 * tq;
            float2 gxr = __half22float2(*(const __half2*)(gp));
            float2 gxz = __half22float2(*(const __half2*)(gp + 8));
            float2 gxn = __half22float2(*(const __half2*)(gp + 16));
            float2 hp = *(const float2*)(hprev32 + m * HH + j0);
            const int q0 = h2 * 2, q1 = q0 + 1;

            float r0 = sigf(acc[mi][0][q0] + gxr.x);
            float r1 = sigf(acc[mi][0][q1] + gxr.y);
            float z0 = sigf(acc[mi][1][q0] + gxz.x);
            float z1 = sigf(acc[mi][1][q1] + gxz.y);
            float nv0 = tanhf(gxn.x + r0 * (acc[mi][2][q0] + bn2.x));
            float nv1 = tanhf(gxn.y + r1 * (acc[mi][2][q1] + bn2.y));
            float h0 = (1.0f - z0) * nv0 + z0 * hp.x;
            float h1 = (1.0f - z1) * nv1 + z1 * hp.y;

            *(float2*)(hnew32 + m * HH + j0) = make_float2(h0, h1);
            __half2 ph = __floats2half2_rn(h0, h1);
            *(uint32_t*)(hnew16 + m * HH + j0) = *(uint32_t*)&ph;
        }
    }
}

// ============================================================
// Fused step: gru (512 CTAs) + pipelined decoder/Gx tail-fill.
// bid: [0,512) gru(t) | [512,640) Wm1(t-1) | [640,672) Wm2(t-2)
//      [672,1056) Gx(t+4) | [1056,1088) Wm3(t-3)
// ============================================================
__global__ void __launch_bounds__(256, 2)
step_fused(int t,
           const half* __restrict__ hin,
           half* __restrict__ hout,
           const float* __restrict__ hprev32,
           float* __restrict__ hnew32,
           const float* __restrict__ bm1,
           const float* __restrict__ bm2,
           const float* __restrict__ bm3,
           float* __restrict__ out)
{
    const int bid = blockIdx.x;
    if (bid < 512) {
        gru_tile(hin, g_Gx + (size_t)(t - 1) * BB * NG3, hprev32, hnew32, hout,
                 bid >> 4, bid & 15);
    } else if (bid < 640) {
        if (t < 2) return;
        int i = bid - 512;
        dec_tile<128, 1>((long)(t - 2) * BB + (long)(i >> 2) * 128, (i & 3) * 128,
                         g_Hd, HH, g_Wm1, HH, bm1, nullptr, HH, g_P1);
    } else if (bid < 672) {
        if (t < 3) return;
        int i = bid - 640;
        dec_tile<64, 1>((long)(t - 3) * BB + (long)i * 128, 0,
                        g_P1, HH, g_Wm2, HH, bm2, nullptr, AA, g_P2);
    } else if (bid < 1056) {
        if (t < 2 || t > 123) return;
        int i = bid - 672;
        dec_tile<128, 0>((long)(t + 3) * BB + (long)(i / 12) * 128, (i % 12) * 128,
                         g_X, AA, g_Wix, AA, g_gxbias, nullptr, NG3, g_Gx);
    } else {
        if (t < 4) return;
        int i = bid - 1056;
        dec_tile<64, 3>((long)(t - 4) * BB + (long)i * 128, 0,
                        g_P2, AA, g_Wm3, AA, bm3, out, 0, nullptr);
    }
}

// ============================================================
// Orchestration
// ============================================================
extern "C" void kernel_launch(void* const* d_in, const int* in_sizes, int n_in,
                              void* d_out, int out_size)
{
    const float* latent = (const float*)d_in[0];
    const float* target = (const float*)d_in[1];
    const float* Wd1 = (const float*)d_in[2];
    const float* bd1 = (const float*)d_in[3];
    const float* Wd2 = (const float*)d_in[4];
    const float* bd2 = (const float*)d_in[5];
    const float* Wd3 = (const float*)d_in[6];
    const float* bd3 = (const float*)d_in[7];
    const float* Wih = (const float*)d_in[8];
    const float* Whh = (const float*)d_in[9];
    const float* bih = (const float*)d_in[10];
    const float* bhh = (const float*)d_in[11];
    const float* Wm1 = (const float*)d_in[12];
    const float* bm1 = (const float*)d_in[13];
    const float* Wm2 = (const float*)d_in[14];
    const float* bm2 = (const float*)d_in[15];
    const float* Wm3 = (const float*)d_in[16];
    const float* bm3 = (const float*)d_in[17];
    float* out = (float*)d_out;

#define SYM(v, s) cudaGetSymbolAddress((void**)&v, s)
    half *Hd, *P1, *P2, *X, *Gx, *H0, *t1, *t2, *L;
    half *Wh3, *Wix, *Wd1h, *Wd2h, *Wd3h, *Wm1h, *Wm2h, *Wm3h;
    float *h32a, *h32b, *gxbias, *bhhn;
    SYM(Hd, g_Hd); SYM(P1, g_P1); SYM(P2, g_P2); SYM(X, g_X); SYM(Gx, g_Gx);
    SYM(H0, g_H0); SYM(t1, g_t1); SYM(t2, g_t2); SYM(L, g_L);
    SYM(Wh3, g_Wh3); SYM(Wix, g_Wix);
    SYM(Wd1h, g_Wd1); SYM(Wd2h, g_Wd2); SYM(Wd3h, g_Wd3);
    SYM(Wm1h, g_Wm1); SYM(Wm2h, g_Wm2); SYM(Wm3h, g_Wm3);
    SYM(h32a, g_h32a); SYM(h32b, g_h32b); SYM(gxbias, g_gxbias); SYM(bhhn, g_bhhn);
#undef SYM

    constexpr int SM128 = 3 * (128 * 72 * 2 + 128 * 72 * 2);   // 110592
    constexpr int SM64  = 3 * (128 * 72 * 2 + 64 * 72 * 2);    // 82944
    constexpr int SMF   = SM128;                               // fused max
    cudaFuncSetAttribute(mma_gemm<128, 0>, cudaFuncAttributeMaxDynamicSharedMemorySize, SM128);
    cudaFuncSetAttribute(mma_gemm<128, 1>, cudaFuncAttributeMaxDynamicSharedMemorySize, SM128);
    cudaFuncSetAttribute(mma_gemm<128, 2>, cudaFuncAttributeMaxDynamicSharedMemorySize, SM128);
    cudaFuncSetAttribute(mma_gemm<64, 1>,  cudaFuncAttributeMaxDynamicSharedMemorySize, SM64);
    cudaFuncSetAttribute(mma_gemm<64, 3>,  cudaFuncAttributeMaxDynamicSharedMemorySize, SM64);
    cudaFuncSetAttribute(step_fused,       cudaFuncAttributeMaxDynamicSharedMemorySize, SMF);

    // ---- setup (4th launch = fused step for ncu profiling) ----
    build_X<<<(int)((M2 * AA) / 256), 256>>>(target, X);                       // 1
    build_Wh3<<<(NG3 * HH + 255) / 256, 256>>>(Whh, Wh3);                      // 2
    build_bhhn<<<(HH + 255) / 256, 256>>>(bhh, bhhn);                          // 3
    // 4: dummy fused step (profiling target). Every output slab it writes is
    // recomputed by a later real launch in this same call.
    step_fused<<<1088, 256, SMF>>>(10, Hd + (size_t)8 * BB * HH,
                                   Hd + (size_t)9 * BB * HH,
                                   h32a, h32b, bm1, bm2, bm3, out);

    build_Wix<<<(NG3 * AA + 255) / 256, 256>>>(Wih, Wix);
    build_gxbias<<<(NG3 + 255) / 256, 256>>>(bih, bhh, gxbias);
    fill_bos_out<<<(BB * AA) / 256, 256>>>(out);
    tohalf<<<(BB * LAT + 255) / 256, 256>>>(latent, L, BB * LAT);
    tohalf<<<(HH * LAT + 255) / 256, 256>>>(Wd1, Wd1h, HH * LAT);
    tohalf<<<(HH * HH + 255) / 256, 256>>>(Wd2, Wd2h, HH * HH);
    tohalf<<<(HH * HH + 255) / 256, 256>>>(Wd3, Wd3h, HH * HH);
    tohalf<<<(HH * HH + 255) / 256, 256>>>(Wm1, Wm1h, HH * HH);
    tohalf<<<(AA * HH + 255) / 256, 256>>>(Wm2, Wm2h, AA * HH);
    tohalf<<<(AA * AA + 255) / 256, 256>>>(Wm3, Wm3h, AA * AA);

    // ---- Gx slabs 1..5 upfront (steps 1-5); rest pipelined in-step ----
    mma_gemm<128, 0><<<dim3(NG3 / 128, 5 * BB / 128), 256, SM128>>>(
        0, X, AA, Wix, AA, gxbias, nullptr, NG3, Gx);

    // ---- h0 = Wd3(tanh(Wd2(tanh(Wd1(latent))))) ----
    mma_gemm<128, 1><<<dim3(HH / 128, BB / 128), 256, SM128>>>(
        0, L, LAT, Wd1h, LAT, bd1, nullptr, HH, t1);
    mma_gemm<128, 1><<<dim3(HH / 128, BB / 128), 256, SM128>>>(
        0, t1, HH, Wd2h, HH, bd2, nullptr, HH, t2);
    mma_gemm<128, 2><<<dim3(HH / 128, BB / 128), 256, SM128>>>(
        0, t2, HH, Wd3h, HH, bd3, h32a, HH, H0);

    // ---- sequential GRU with fused decoder/Gx tail-fill ----
    float* hp32 = h32a;
    float* hn32 = h32b;
    for (int t = 1; t < LL; ++t) {
        const half* hin = (t == 1) ? H0 : Hd + (size_t)(t - 2) * BB * HH;
        step_fused<<<1088, 256, SMF>>>(t, hin,
                                       Hd + (size_t)(t - 1) * BB * HH,
                                       hp32, hn32, bm1, bm2, bm3, out);
        float* tmp = hp32; hp32 = hn32; hn32 = tmp;
    }

    // ---- drain: Wm1 slab 127; Wm2 slabs 126-127; Wm3 slabs 125-127 ----
    mma_gemm<128, 1><<<dim3(HH / 128, BB / 128), 256, SM128>>>(
        (long)126 * BB, Hd, HH, Wm1h, HH, bm1, nullptr, HH, P1);
    mma_gemm<64, 1><<<dim3(1, 2 * BB / 128), 256, SM64>>>(
        (long)125 * BB, P1, HH, Wm2h, HH, bm2, nullptr, AA, P2);
    mma_gemm<64, 3><<<dim3(1, 3 * BB / 128), 256, SM64>>>(
        (long)124 * BB, P2, AA, Wm3h, AA, bm3, out, 0, nullptr);
}

// round 12
// speedup vs baseline: 6.6421x; 1.0833x over previous
#include <cuda_runtime.h>
#include <cuda_fp16.h>
#include <math.h>
#include <stdint.h>

#define BB 4096
#define LAT 256
#define HH 512
#define AA 64
#define LL 128
#define NG3 1536         // gate layout: 64 groups x [r8|z8|n8]
#define M2 ((long)(LL - 1) * BB)   // 520192

// ---- scratch (static device globals; ~4.0 GB) ----
__device__ half  g_Hd[(size_t)(LL - 1) * BB * HH];     // h_t fp16, slots t=1..127
__device__ half  g_P1[(size_t)(LL - 1) * BB * HH];
__device__ half  g_P2[(size_t)(LL - 1) * BB * AA];
__device__ half  g_X[(size_t)(LL - 1) * BB * AA];
__device__ half  g_Gx[(size_t)(LL - 1) * BB * NG3];    // precomputed x-gates (+bias)
__device__ float g_h32a[(size_t)BB * HH];
__device__ float g_h32b[(size_t)BB * HH];
__device__ half  g_H0[(size_t)BB * HH];
__device__ half  g_t1[(size_t)BB * HH];
__device__ half  g_t2[(size_t)BB * HH];
__device__ half  g_L[(size_t)BB * LAT];
__device__ half  g_Wh3[(size_t)NG3 * HH];              // interleaved Whh
__device__ half  g_Wix[(size_t)NG3 * AA];              // interleaved Wih (r,z,nx)
__device__ half  g_Wd1[HH * LAT];
__device__ half  g_Wd2[HH * HH];
__device__ half  g_Wd3[HH * HH];
__device__ half  g_Wm1[HH * HH];
__device__ half  g_Wm2[AA * HH];
__device__ half  g_Wm3[AA * AA];
__device__ float g_gxbias[NG3];
__device__ float g_bhhn[HH];

// ============================================================
// helpers
// ============================================================
__device__ __forceinline__ uint32_t smem_u32(const void* p) {
    uint32_t a;
    asm("{ .reg .u64 t; cvta.to.shared.u64 t, %1; cvt.u32.u64 %0, t; }" : "=r"(a) : "l"(p));
    return a;
}
__device__ __forceinline__ void cpa16(uint32_t dst, const void* src) {
    asm volatile("cp.async.cg.shared.global [%0], [%1], 16;" :: "r"(dst), "l"(src));
}
__device__ __forceinline__ void cpa_commit() {
    asm volatile("cp.async.commit_group;" ::: "memory");
}
__device__ __forceinline__ void cpa_wait1() {
    asm volatile("cp.async.wait_group 1;" ::: "memory");
}
__device__ __forceinline__ float sigf(float x) { return 1.0f / (1.0f + expf(-x)); }

__device__ __forceinline__ void mma16(float d[4], const uint32_t a[4], const uint32_t b[2]) {
    asm volatile(
        "mma.sync.aligned.m16n8k16.row.col.f32.f16.f16.f32 "
        "{%0,%1,%2,%3},{%4,%5,%6,%7},{%8,%9},{%0,%1,%2,%3};"
        : "+f"(d[0]), "+f"(d[1]), "+f"(d[2]), "+f"(d[3])
        : "r"(a[0]), "r"(a[1]), "r"(a[2]), "r"(a[3]), "r"(b[0]), "r"(b[1]));
}
__device__ __forceinline__ void ldsm_x4(uint32_t r[4], uint32_t addr) {
    asm volatile("ldmatrix.sync.aligned.m8n8.x4.shared.b16 {%0,%1,%2,%3}, [%4];"
                 : "=r"(r[0]), "=r"(r[1]), "=r"(r[2]), "=r"(r[3]) : "r"(addr));
}
__device__ __forceinline__ void ldsm_x2(uint32_t r[2], uint32_t addr) {
    asm volatile("ldmatrix.sync.aligned.m8n8.x2.shared.b16 {%0,%1}, [%2];"
                 : "=r"(r[0]), "=r"(r[1]) : "r"(addr));
}

// ============================================================
// Setup kernels
// ============================================================
__global__ void fill_bos_out(float* __restrict__ out) {
    int idx = blockIdx.x * blockDim.x + threadIdx.x;
    int b = idx >> 6, a = idx & 63;
    out[(size_t)b * (LL * AA) + a] = (a == 0) ? 16.0f : -16.0f;
}
__global__ void build_X(const float* __restrict__ target, half* __restrict__ X) {
    size_t idx = (size_t)blockIdx.x * blockDim.x + threadIdx.x;
    int a = (int)(idx & 63);
    size_t row = idx >> 6;
    int trow = (int)(row >> 12);
    int b = (int)(row & 4095);
    float v;
    if (trow == 0) v = (a == 0) ? 16.0f : -16.0f;
    else           v = target[((size_t)b << 13) + (size_t)trow * AA + a];
    X[idx] = __float2half_rn(v);
}
__global__ void tohalf(const float* __restrict__ src, half* __restrict__ dst, int n) {
    int i = blockIdx.x * blockDim.x + threadIdx.x;
    if (i < n) dst[i] = __float2half_rn(src[i]);
}
__global__ void build_Wh3(const float* __restrict__ Whh, half* __restrict__ w) {
    int i = blockIdx.x * blockDim.x + threadIdx.x;
    if (i >= NG3 * HH) return;
    int k = i & 511, c = i >> 9;
    int g = c / 24, r = c % 24;
    int type = r >> 3, j = 8 * g + (r & 7);
    w[i] = __float2half_rn(Whh[(size_t)(type * 512 + j) * HH + k]);
}
__global__ void build_Wix(const float* __restrict__ Wih, half* __restrict__ w) {
    int i = blockIdx.x * blockDim.x + threadIdx.x;
    if (i >= NG3 * AA) return;
    int k = i & 63, c = i >> 6;
    int g = c / 24, r = c % 24;
    int type = r >> 3, j = 8 * g + (r & 7);
    w[i] = __float2half_rn(Wih[(type * 512 + j) * AA + k]);
}
__global__ void build_gxbias(const float* __restrict__ bih, const float* __restrict__ bhh,
                             float* __restrict__ bc) {
    int c = blockIdx.x * blockDim.x + threadIdx.x;
    if (c >= NG3) return;
    int g = c / 24, r = c % 24;
    int type = r >> 3, j = 8 * g + (r & 7);
    float v;
    if (type == 0)      v = bih[j] + bhh[j];
    else if (type == 1) v = bih[512 + j] + bhh[512 + j];
    else                v = bih[1024 + j];
    bc[c] = v;
}
__global__ void build_bhhn(const float* __restrict__ bhh, float* __restrict__ bn) {
    int j = blockIdx.x * blockDim.x + threadIdx.x;
    if (j < HH) bn[j] = bhh[1024 + j];
}

// ============================================================
// dec_tile: one BM=128 x BN GEMM tile, fp16 in, fp32 acc.
// 512 threads, warp grid 4M x 4N (warp tile 32 x BN/4), MI=2.
// 3-stage cp.async, ldmatrix, one __syncthreads per chunk.
// EPI: 0 = fp16 store; 1 = tanh->fp16; 2 = f32 + fp16; 3 = scatter f32.
// ============================================================
template <int BN, int EPI>
__device__ __forceinline__ void dec_tile(
    long m0, int n0,
    const half* __restrict__ A_g, long lda,
    const half* __restrict__ B_g, int K,
    const float* __restrict__ bias,
    float* __restrict__ Cf, long ldc,
    half* __restrict__ Ch)
{
    constexpr int SS = 72;
    constexpr int MI = 2;
    constexpr int WN = BN / 4;           // 32 or 16
    constexpr int NI = WN / 8;           // 4 or 2
    constexpr int ABYT = 128 * SS * 2;
    constexpr int BBYT = BN * SS * 2;
    constexpr int BUF = ABYT + BBYT;

    extern __shared__ char smem[];
    const uint32_t sb = smem_u32(smem);

    const int tid = threadIdx.x;
    const int wid = tid >> 5, lane = tid & 31;
    const int wm = wid & 3, wn = wid >> 2;
    const int gr = lane >> 2, tq = lane & 3;
    const int aro = (lane & 7) + ((lane >> 3) & 1) * 8;
    const int aco = (lane >> 4) * 8;
    const int bro = ((lane >> 4) & 1) * 8 + (lane & 7);
    const int bko = ((lane >> 3) & 1) * 8;

    const int nc = K >> 6;

    float acc[MI][NI][4];
#pragma unroll
    for (int mi = 0; mi < MI; ++mi)
#pragma unroll
        for (int ni = 0; ni < NI; ++ni)
#pragma unroll
            for (int q = 0; q < 4; ++q) acc[mi][ni][q] = 0.0f;

    auto load_chunk = [&](int ch) {
        const int k0 = ch << 6;
        const uint32_t base = sb + (ch % 3) * BUF;
#pragma unroll
        for (int it = 0; it < 2; ++it) {
            int e = tid + it * 512;
            int row = e >> 3, seg = e & 7;
            cpa16(base + (uint32_t)(row * SS + seg * 8) * 2,
                  A_g + (m0 + row) * lda + k0 + seg * 8);
        }
#pragma unroll
        for (int it = 0; it < BN / 64; ++it) {
            int e = tid + it * 512;
            int row = e >> 3, seg = e & 7;
            cpa16(base + ABYT + (uint32_t)(row * SS + seg * 8) * 2,
                  B_g + (long)(n0 + row) * K + k0 + seg * 8);
        }
    };

    load_chunk(0); cpa_commit();
    if (nc > 1) load_chunk(1);
    cpa_commit();

    for (int ch = 0; ch < nc; ++ch) {
        cpa_wait1();
        __syncthreads();
        if (ch + 2 < nc) load_chunk(ch + 2);
        cpa_commit();

        const uint32_t aBase = sb + (ch % 3) * BUF;
        const uint32_t bBase = aBase + ABYT;

#pragma unroll
        for (int k16 = 0; k16 < 4; ++k16) {
            const int kk = k16 * 16;
            uint32_t af[MI][4], bf[NI][2];
#pragma unroll
            for (int mi = 0; mi < MI; ++mi)
                ldsm_x4(af[mi], aBase + (uint32_t)((wm * 32 + mi * 16 + aro) * SS + kk + aco) * 2);
#pragma unroll
            for (int n2 = 0; n2 < NI / 2; ++n2)
                ldsm_x4(&bf[2 * n2][0], bBase + (uint32_t)((wn * WN + n2 * 16 + bro) * SS + kk + bko) * 2);
#pragma unroll
            for (int mi = 0; mi < MI; ++mi)
#pragma unroll
                for (int ni = 0; ni < NI; ++ni)
                    mma16(acc[mi][ni], af[mi], bf[ni]);
        }
    }

#pragma unroll
    for (int mi = 0; mi < MI; ++mi) {
#pragma unroll
        for (int ni = 0; ni < NI; ++ni) {
            const int col = n0 + wn * WN + ni * 8 + 2 * tq;
            const long mA = m0 + wm * 32 + mi * 16 + gr;
            float2 bc = *(const float2*)(bias + col);
            float v0 = acc[mi][ni][0] + bc.x;
            float v1 = acc[mi][ni][1] + bc.y;
            float v2 = acc[mi][ni][2] + bc.x;
            float v3 = acc[mi][ni][3] + bc.y;

            if (EPI <= 2) {
                if (EPI == 1) { v0 = tanhf(v0); v1 = tanhf(v1); v2 = tanhf(v2); v3 = tanhf(v3); }
                if (EPI == 2) {
                    *(float2*)(Cf + mA * ldc + col) = make_float2(v0, v1);
                    *(float2*)(Cf + (mA + 8) * ldc + col) = make_float2(v2, v3);
                }
                __half2 p0 = __floats2half2_rn(v0, v1);
                __half2 p1 = __floats2half2_rn(v2, v3);
                *(uint32_t*)(Ch + mA * ldc + col) = *(uint32_t*)&p0;
                *(uint32_t*)(Ch + (mA + 8) * ldc + col) = *(uint32_t*)&p1;
            } else {
                long t1_ = (mA >> 12) + 1, b1_ = mA & 4095;
                long t2_ = ((mA + 8) >> 12) + 1, b2_ = (mA + 8) & 4095;
                *(float2*)(Cf + b1_ * (LL * AA) + t1_ * AA + col) = make_float2(v0, v1);
                *(float2*)(Cf + b2_ * (LL * AA) + t2_ * AA + col) = make_float2(v2, v3);
            }
        }
    }
}

// standalone GEMM wrapper (mrow0 = global row offset)
template <int BN, int EPI>
__global__ void __launch_bounds__(512, 2)
mma_gemm(long mrow0,
         const half* __restrict__ A_g, long lda,
         const half* __restrict__ B_g, int K,
         const float* __restrict__ bias,
         float* __restrict__ Cf, long ldc,
         half* __restrict__ Ch)
{
    dec_tile<BN, EPI>(mrow0 + (long)blockIdx.y * 128, blockIdx.x * BN,
                      A_g, lda, B_g, K, bias, Cf, ldc, Ch);
}

// ============================================================
// gru_tile: one 128x96 tile of Ghh = h @ Wh3^T + fused GRU epilogue.
// 512 threads, warp grid 4M x 4N (warp tile 32 x 24 = [r8|z8|n8]), MI=2, NI=3.
// ============================================================
__device__ __forceinline__ void gru_tile(
    const half* __restrict__ A_g,      // hprev fp16 [BB,512]
    const half* __restrict__ gx,       // Gx slab [BB,1536]
    const float* __restrict__ hprev32,
    float* __restrict__ hnew32,
    half* __restrict__ hnew16,
    int mbk, int nbk)
{
    constexpr int SS = 72;
    constexpr int MI = 2;
    constexpr int NI = 3;
    constexpr int ABYT = 128 * SS * 2;
    constexpr int BBYT = 96 * SS * 2;
    constexpr int BUF = ABYT + BBYT;
    constexpr int nc = HH >> 6;

    extern __shared__ char smem[];
    const uint32_t sb = smem_u32(smem);

    const int tid = threadIdx.x;
    const int wid = tid >> 5, lane = tid & 31;
    const int wm = wid & 3, wn = wid >> 2;
    const int gr = lane >> 2, tq = lane & 3;
    const int aro = (lane & 7) + ((lane >> 3) & 1) * 8;
    const int aco = (lane >> 4) * 8;
    const int bro = ((lane >> 4) & 1) * 8 + (lane & 7);
    const int bko = ((lane >> 3) & 1) * 8;
    const int b2ro = 16 + (lane & 7);
    const int b2ko = ((lane >> 3) & 1) * 8;

    const long m0 = (long)mbk * 128;
    const int  n0 = nbk * 96;
    const half* B_g = g_Wh3;

    float acc[MI][NI][4];
#pragma unroll
    for (int mi = 0; mi < MI; ++mi)
#pragma unroll
        for (int ni = 0; ni < NI; ++ni)
#pragma unroll
            for (int q = 0; q < 4; ++q) acc[mi][ni][q] = 0.0f;

    auto load_chunk = [&](int ch) {
        const int k0 = ch << 6;
        const uint32_t base = sb + (ch % 3) * BUF;
#pragma unroll
        for (int it = 0; it < 2; ++it) {
            int e = tid + it * 512;
            int row = e >> 3, seg = e & 7;
            cpa16(base + (uint32_t)(row * SS + seg * 8) * 2,
                  A_g + (m0 + row) * (long)HH + k0 + seg * 8);
        }
#pragma unroll
        for (int it = 0; it < 2; ++it) {
            int e = tid + it * 512;
            if (e < 96 * 8) {
                int row = e >> 3, seg = e & 7;
                cpa16(base + ABYT + (uint32_t)(row * SS + seg * 8) * 2,
                      B_g + (long)(n0 + row) * HH + k0 + seg * 8);
            }
        }
    };

    load_chunk(0); cpa_commit();
    load_chunk(1); cpa_commit();

    for (int ch = 0; ch < nc; ++ch) {
        cpa_wait1();
        __syncthreads();
        if (ch + 2 < nc) load_chunk(ch + 2);
        cpa_commit();

        const uint32_t aBase = sb + (ch % 3) * BUF;
        const uint32_t bBase = aBase + ABYT;

#pragma unroll
        for (int k16 = 0; k16 < 4; ++k16) {
            const int kk = k16 * 16;
            uint32_t af[MI][4], bf[NI][2];
#pragma unroll
            for (int mi = 0; mi < MI; ++mi)
                ldsm_x4(af[mi], aBase + (uint32_t)((wm * 32 + mi * 16 + aro) * SS + kk + aco) * 2);
            ldsm_x4(&bf[0][0], bBase + (uint32_t)((wn * 24 + bro) * SS + kk + bko) * 2);
            ldsm_x2(&bf[2][0], bBase + (uint32_t)((wn * 24 + b2ro) * SS + kk + b2ko) * 2);
#pragma unroll
            for (int mi = 0; mi < MI; ++mi)
#pragma unroll
                for (int ni = 0; ni < NI; ++ni)
                    mma16(acc[mi][ni], af[mi], bf[ni]);
        }
    }

    const int jb = 8 * (4 * nbk + wn);
    const int j0 = jb + 2 * tq;
    const float2 bn2 = *(const float2*)(g_bhhn + j0);

#pragma unroll
    for (int mi = 0; mi < MI; ++mi) {
#pragma unroll
        for (int h2 = 0; h2 < 2; ++h2) {
            const long m = m0 + wm * 32 + mi * 16 + gr + h2 * 8;
            const half* gp = gx + m * NG3 + n0 + wn * 24 + 2 * tq;
            float2 gxr = __half22float2(*(const __half2*)(gp));
            float2 gxz = __half22float2(*(const __half2*)(gp + 8));
            float2 gxn = __half22float2(*(const __half2*)(gp + 16));
            float2 hp = *(const float2*)(hprev32 + m * HH + j0);
            const int q0 = h2 * 2, q1 = q0 + 1;

            float r0 = sigf(acc[mi][0][q0] + gxr.x);
            float r1 = sigf(acc[mi][0][q1] + gxr.y);
            float z0 = sigf(acc[mi][1][q0] + gxz.x);
            float z1 = sigf(acc[mi][1][q1] + gxz.y);
            float nv0 = tanhf(gxn.x + r0 * (acc[mi][2][q0] + bn2.x));
            float nv1 = tanhf(gxn.y + r1 * (acc[mi][2][q1] + bn2.y));
            float h0 = (1.0f - z0) * nv0 + z0 * hp.x;
            float h1 = (1.0f - z1) * nv1 + z1 * hp.y;

            *(float2*)(hnew32 + m * HH + j0) = make_float2(h0, h1);
            __half2 ph = __floats2half2_rn(h0, h1);
            *(uint32_t*)(hnew16 + m * HH + j0) = *(uint32_t*)&ph;
        }
    }
}

// ============================================================
// Fused step: gru (512 CTAs) + pipelined decoder/Gx tail-fill.
// bid: [0,512) gru(t) | [512,640) Wm1(t-1) | [640,672) Wm2(t-2)
//      [672,1056) Gx(t+4) | [1056,1088) Wm3(t-3)
// ============================================================
__global__ void __launch_bounds__(512, 2)
step_fused(int t,
           const half* __restrict__ hin,
           half* __restrict__ hout,
           const float* __restrict__ hprev32,
           float* __restrict__ hnew32,
           const float* __restrict__ bm1,
           const float* __restrict__ bm2,
           const float* __restrict__ bm3,
           float* __restrict__ out)
{
    const int bid = blockIdx.x;
    if (bid < 512) {
        gru_tile(hin, g_Gx + (size_t)(t - 1) * BB * NG3, hprev32, hnew32, hout,
                 bid >> 4, bid & 15);
    } else if (bid < 640) {
        if (t < 2) return;
        int i = bid - 512;
        dec_tile<128, 1>((long)(t - 2) * BB + (long)(i >> 2) * 128, (i & 3) * 128,
                         g_Hd, HH, g_Wm1, HH, bm1, nullptr, HH, g_P1);
    } else if (bid < 672) {
        if (t < 3) return;
        int i = bid - 640;
        dec_tile<64, 1>((long)(t - 3) * BB + (long)i * 128, 0,
                        g_P1, HH, g_Wm2, HH, bm2, nullptr, AA, g_P2);
    } else if (bid < 1056) {
        if (t < 2 || t > 123) return;
        int i = bid - 672;
        dec_tile<128, 0>((long)(t + 3) * BB + (long)(i / 12) * 128, (i % 12) * 128,
                         g_X, AA, g_Wix, AA, g_gxbias, nullptr, NG3, g_Gx);
    } else {
        if (t < 4) return;
        int i = bid - 1056;
        dec_tile<64, 3>((long)(t - 4) * BB + (long)i * 128, 0,
                        g_P2, AA, g_Wm3, AA, bm3, out, 0, nullptr);
    }
}

// ============================================================
// Orchestration
// ============================================================
extern "C" void kernel_launch(void* const* d_in, const int* in_sizes, int n_in,
                              void* d_out, int out_size)
{
    const float* latent = (const float*)d_in[0];
    const float* target = (const float*)d_in[1];
    const float* Wd1 = (const float*)d_in[2];
    const float* bd1 = (const float*)d_in[3];
    const float* Wd2 = (const float*)d_in[4];
    const float* bd2 = (const float*)d_in[5];
    const float* Wd3 = (const float*)d_in[6];
    const float* bd3 = (const float*)d_in[7];
    const float* Wih = (const float*)d_in[8];
    const float* Whh = (const float*)d_in[9];
    const float* bih = (const float*)d_in[10];
    const float* bhh = (const float*)d_in[11];
    const float* Wm1 = (const float*)d_in[12];
    const float* bm1 = (const float*)d_in[13];
    const float* Wm2 = (const float*)d_in[14];
    const float* bm2 = (const float*)d_in[15];
    const float* Wm3 = (const float*)d_in[16];
    const float* bm3 = (const float*)d_in[17];
    float* out = (float*)d_out;

#define SYM(v, s) cudaGetSymbolAddress((void**)&v, s)
    half *Hd, *P1, *P2, *X, *Gx, *H0, *t1, *t2, *L;
    half *Wh3, *Wix, *Wd1h, *Wd2h, *Wd3h, *Wm1h, *Wm2h, *Wm3h;
    float *h32a, *h32b, *gxbias, *bhhn;
    SYM(Hd, g_Hd); SYM(P1, g_P1); SYM(P2, g_P2); SYM(X, g_X); SYM(Gx, g_Gx);
    SYM(H0, g_H0); SYM(t1, g_t1); SYM(t2, g_t2); SYM(L, g_L);
    SYM(Wh3, g_Wh3); SYM(Wix, g_Wix);
    SYM(Wd1h, g_Wd1); SYM(Wd2h, g_Wd2); SYM(Wd3h, g_Wd3);
    SYM(Wm1h, g_Wm1); SYM(Wm2h, g_Wm2); SYM(Wm3h, g_Wm3);
    SYM(h32a, g_h32a); SYM(h32b, g_h32b); SYM(gxbias, g_gxbias); SYM(bhhn, g_bhhn);
#undef SYM

    constexpr int SM128 = 3 * (128 * 72 * 2 + 128 * 72 * 2);   // 110592
    constexpr int SM64  = 3 * (128 * 72 * 2 + 64 * 72 * 2);    // 82944
    constexpr int SMF   = SM128;
    cudaFuncSetAttribute(mma_gemm<128, 0>, cudaFuncAttributeMaxDynamicSharedMemorySize, SM128);
    cudaFuncSetAttribute(mma_gemm<128, 1>, cudaFuncAttributeMaxDynamicSharedMemorySize, SM128);
    cudaFuncSetAttribute(mma_gemm<128, 2>, cudaFuncAttributeMaxDynamicSharedMemorySize, SM128);
    cudaFuncSetAttribute(mma_gemm<64, 1>,  cudaFuncAttributeMaxDynamicSharedMemorySize, SM64);
    cudaFuncSetAttribute(mma_gemm<64, 3>,  cudaFuncAttributeMaxDynamicSharedMemorySize, SM64);
    cudaFuncSetAttribute(step_fused,       cudaFuncAttributeMaxDynamicSharedMemorySize, SMF);

    // ---- setup (4th launch = fused step for ncu profiling) ----
    build_X<<<(int)((M2 * AA) / 256), 256>>>(target, X);                       // 1
    build_Wh3<<<(NG3 * HH + 255) / 256, 256>>>(Whh, Wh3);                      // 2
    build_bhhn<<<(HH + 255) / 256, 256>>>(bhh, bhhn);                          // 3
    // 4: dummy fused step (profiling target). Every output slab it writes is
    // recomputed by a later real launch in this same call.
    step_fused<<<1088, 512, SMF>>>(10, Hd + (size_t)8 * BB * HH,
                                   Hd + (size_t)9 * BB * HH,
                                   h32a, h32b, bm1, bm2, bm3, out);

    build_Wix<<<(NG3 * AA + 255) / 256, 256>>>(Wih, Wix);
    build_gxbias<<<(NG3 + 255) / 256, 256>>>(bih, bhh, gxbias);
    fill_bos_out<<<(BB * AA) / 256, 256>>>(out);
    tohalf<<<(BB * LAT + 255) / 256, 256>>>(latent, L, BB * LAT);
    tohalf<<<(HH * LAT + 255) / 256, 256>>>(Wd1, Wd1h, HH * LAT);
    tohalf<<<(HH * HH + 255) / 256, 256>>>(Wd2, Wd2h, HH * HH);
    tohalf<<<(HH * HH + 255) / 256, 256>>>(Wd3, Wd3h, HH * HH);
    tohalf<<<(HH * HH + 255) / 256, 256>>>(Wm1, Wm1h, HH * HH);
    tohalf<<<(AA * HH + 255) / 256, 256>>>(Wm2, Wm2h, AA * HH);
    tohalf<<<(AA * AA + 255) / 256, 256>>>(Wm3, Wm3h, AA * AA);

    // ---- Gx slabs 1..5 upfront (steps 1-5); rest pipelined in-step ----
    mma_gemm<128, 0><<<dim3(NG3 / 128, 5 * BB / 128), 512, SM128>>>(
        0, X, AA, Wix, AA, gxbias, nullptr, NG3, Gx);

    // ---- h0 = Wd3(tanh(Wd2(tanh(Wd1(latent))))) ----
    mma_gemm<128, 1><<<dim3(HH / 128, BB / 128), 512, SM128>>>(
        0, L, LAT, Wd1h, LAT, bd1, nullptr, HH, t1);
    mma_gemm<128, 1><<<dim3(HH / 128, BB / 128), 512, SM128>>>(
        0, t1, HH, Wd2h, HH, bd2, nullptr, HH, t2);
    mma_gemm<128, 2><<<dim3(HH / 128, BB / 128), 512, SM128>>>(
        0, t2, HH, Wd3h, HH, bd3, h32a, HH, H0);

    // ---- sequential GRU with fused decoder/Gx tail-fill ----
    float* hp32 = h32a;
    float* hn32 = h32b;
    for (int t = 1; t < LL; ++t) {
        const half* hin = (t == 1) ? H0 : Hd + (size_t)(t - 2) * BB * HH;
        step_fused<<<1088, 512, SMF>>>(t, hin,
                                       Hd + (size_t)(t - 1) * BB * HH,
                                       hp32, hn32, bm1, bm2, bm3, out);
        float* tmp = hp32; hp32 = hn32; hn32 = tmp;
    }

    // ---- drain: Wm1 slab 127; Wm2 slabs 126-127; Wm3 slabs 125-127 ----
    mma_gemm<128, 1><<<dim3(HH / 128, BB / 128), 512, SM128>>>(
        (long)126 * BB, Hd, HH, Wm1h, HH, bm1, nullptr, HH, P1);
    mma_gemm<64, 1><<<dim3(1, 2 * BB / 128), 512, SM64>>>(
        (long)125 * BB, P1, HH, Wm2h, HH, bm2, nullptr, AA, P2);
    mma_gemm<64, 3><<<dim3(1, 3 * BB / 128), 512, SM64>>>(
        (long)124 * BB, P2, AA, Wm3h, AA, bm3, out, 0, nullptr);
}